// round 4
// baseline (speedup 1.0000x reference)
#include <cuda_runtime.h>
#include <cuda_bf16.h>
#include <cstdint>

// Problem constants
// x: [8,64,64,512] f32; w_theta [512,64]; w_phi [512,64]; w_g [512,256]; w_o [256,512]; gamma [1]
// out: [8,64,64,512] f32
#define M_TOT   32768      // 8*4096 rows
#define C_IN    512
#define CK      64
#define CV      256
#define NPROJ   384        // theta(64) + phi(64) + g(256)
#define NKV     320        // phi(64) + g(256) pooled
#define HW      4096
#define HWP     1024

// Scratch (device globals; allocation is forbidden)
__device__ __nv_bfloat16 g_Y[(size_t)M_TOT * NPROJ];    // proj outputs (bf16)
__device__ __nv_bfloat16 g_KV[(size_t)8 * HWP * NKV];   // pooled phi|g
__device__ __nv_bfloat16 g_O[(size_t)M_TOT * CV];       // attn output (bf16)

// ---------------------------------------------------------------------------
// mma.sync m16n8k16 bf16 (row.col), f32 accumulate
// A frag (row-major 16x16): a0=(m=g,k=2t..), a1=(m=g+8), a2=(k+8), a3=(m+8,k+8)
// B frag (col-major 16x8 = B[k][n], k-contig per n): b0=(k=2t..,n=g), b1=(k+8)
// C/D: c0=(m=g,n=2t) c1=(n=2t+1) c2=(m+8) c3=(m+8,n+1)
// ---------------------------------------------------------------------------
__device__ __forceinline__ void mma16816(float* d, const unsigned* a, const unsigned* b) {
    asm volatile(
        "mma.sync.aligned.m16n8k16.row.col.f32.bf16.bf16.f32 "
        "{%0,%1,%2,%3}, {%4,%5,%6,%7}, {%8,%9}, {%0,%1,%2,%3};\n"
        : "+f"(d[0]), "+f"(d[1]), "+f"(d[2]), "+f"(d[3])
        : "r"(a[0]), "r"(a[1]), "r"(a[2]), "r"(a[3]), "r"(b[0]), "r"(b[1]));
}

// ===========================================================================
// K1: proj GEMM  Y[32768,384] = bf16( X[32768,512] @ Wcat[512,384] )
// CTA tile 128x64, 8 warps (4 M x 2 N), warp tile 32x32, K-chunk 32.
// Smem A [128][40], B [64][40] (pad 8 -> conflict-free 32-bit LDS).
// ===========================================================================
__global__ __launch_bounds__(256) void proj_kernel(
    const float* __restrict__ x,
    const float* __restrict__ w_theta,
    const float* __restrict__ w_phi,
    const float* __restrict__ w_g)
{
    __shared__ __nv_bfloat16 As[128][40];
    __shared__ __nv_bfloat16 Bs[64][40];

    const int m0 = blockIdx.y * 128;
    const int n0 = blockIdx.x * 64;

    const float* wptr; int ld, col0;
    if (n0 < 64)       { wptr = w_theta; ld = CK; col0 = n0;       }
    else if (n0 < 128) { wptr = w_phi;   ld = CK; col0 = n0 - 64;  }
    else               { wptr = w_g;     ld = CV; col0 = n0 - 128; }

    const int tid  = threadIdx.x;
    const int warp = tid >> 5, lane = tid & 31;
    const int wm = warp >> 1, wn = warp & 1;        // 4 x 2 warps
    const int g = lane >> 2, t = lane & 3;

    float acc[2][4][4];
    #pragma unroll
    for (int mi = 0; mi < 2; mi++)
        #pragma unroll
        for (int ni = 0; ni < 4; ni++)
            #pragma unroll
            for (int j = 0; j < 4; j++) acc[mi][ni][j] = 0.f;

    const int ra = tid >> 3;            // A-load: row 0..31 (x4 passes)
    const int ca = (tid & 7) * 4;       // col 0..28 step 4 (float4)
    const int ib = tid & 63;            // B-load: n index
    const int kb = (tid >> 6) * 8;      // k sub-block

    for (int kc = 0; kc < C_IN; kc += 32) {
        // A: 128x32 fp32 -> bf16
        #pragma unroll
        for (int rr = 0; rr < 128; rr += 32) {
            float4 v = *(const float4*)&x[(size_t)(m0 + rr + ra) * C_IN + kc + ca];
            __nv_bfloat162* dst = (__nv_bfloat162*)&As[rr + ra][ca];
            dst[0] = __floats2bfloat162_rn(v.x, v.y);
            dst[1] = __floats2bfloat162_rn(v.z, v.w);
        }
        // B: 64x32, transpose to [n][k]
        #pragma unroll
        for (int kk = 0; kk < 8; kk++)
            Bs[ib][kb + kk] = __float2bfloat16(wptr[(size_t)(kc + kb + kk) * ld + col0 + ib]);
        __syncthreads();

        #pragma unroll
        for (int k16 = 0; k16 < 32; k16 += 16) {
            unsigned a[2][4], bf[4][2];
            #pragma unroll
            for (int mi = 0; mi < 2; mi++) {
                int r = wm * 32 + mi * 16 + g;
                a[mi][0] = *(const unsigned*)&As[r    ][k16 + 2*t    ];
                a[mi][1] = *(const unsigned*)&As[r + 8][k16 + 2*t    ];
                a[mi][2] = *(const unsigned*)&As[r    ][k16 + 2*t + 8];
                a[mi][3] = *(const unsigned*)&As[r + 8][k16 + 2*t + 8];
            }
            #pragma unroll
            for (int ni = 0; ni < 4; ni++) {
                int n = wn * 32 + ni * 8 + g;
                bf[ni][0] = *(const unsigned*)&Bs[n][k16 + 2*t    ];
                bf[ni][1] = *(const unsigned*)&Bs[n][k16 + 2*t + 8];
            }
            #pragma unroll
            for (int mi = 0; mi < 2; mi++)
                #pragma unroll
                for (int ni = 0; ni < 4; ni++)
                    mma16816(acc[mi][ni], a[mi], bf[ni]);
        }
        __syncthreads();
    }

    // Epilogue -> g_Y (bf16)
    #pragma unroll
    for (int mi = 0; mi < 2; mi++)
        #pragma unroll
        for (int ni = 0; ni < 4; ni++) {
            int row = m0 + wm * 32 + mi * 16 + g;
            int col = n0 + wn * 32 + ni * 8 + 2 * t;
            *(__nv_bfloat162*)&g_Y[(size_t)row * NPROJ + col] =
                __floats2bfloat162_rn(acc[mi][ni][0], acc[mi][ni][1]);
            *(__nv_bfloat162*)&g_Y[(size_t)(row + 8) * NPROJ + col] =
                __floats2bfloat162_rn(acc[mi][ni][2], acc[mi][ni][3]);
        }
}

// ===========================================================================
// K2: 2x2 maxpool of Y[:,64:384] -> KV[8,1024,320]
// ===========================================================================
__global__ __launch_bounds__(256) void pool_kernel()
{
    int idx = blockIdx.x * 256 + threadIdx.x;
    const int total = 8 * HWP * NKV;
    if (idx >= total) return;
    int j  = idx % NKV;
    int pp = (idx / NKV) % HWP;
    int b  = idx / (NKV * HWP);
    int h2 = pp >> 5, w2 = pp & 31;
    size_t base = (size_t)b * HW;
    float m = -1e30f;
    #pragma unroll
    for (int dh = 0; dh < 2; dh++)
        #pragma unroll
        for (int dw = 0; dw < 2; dw++) {
            int p = (2*h2 + dh) * 64 + 2*w2 + dw;
            float v = __bfloat162float(g_Y[(base + p) * NPROJ + 64 + j]);
            m = fmaxf(m, v);
        }
    g_KV[idx] = __float2bfloat16(m);
}

// ===========================================================================
// K3: fused attention per (batch, 32-query tile)
//   S[32,1024] = Q KphiT (smem fp32) -> softmax -> P bf16 -> O = P @ V
// Smem (dynamic 220672 B):
//   Qs bf16[32][72]     @ 0
//   Ks bf16[128][72]    @ 4608
//   Ss f32 [32][1028]   @ 23040   (aliased by Vs bf16[256][136] in phase 3)
//   Ps bf16[32][1032]   @ 154624
// ===========================================================================
#define ATTN_SMEM 220672

__global__ __launch_bounds__(256) void attn_kernel()
{
    extern __shared__ unsigned char sm[];
    __nv_bfloat16* Qs = (__nv_bfloat16*)(sm);
    __nv_bfloat16* Ks = (__nv_bfloat16*)(sm + 4608);
    float*         Ss = (float*)(sm + 23040);
    __nv_bfloat16* Vs = (__nv_bfloat16*)(sm + 23040);
    __nv_bfloat16* Ps = (__nv_bfloat16*)(sm + 154624);

    const int tid = threadIdx.x, warp = tid >> 5, lane = tid & 31;
    const int g = lane >> 2, t = lane & 3;
    const int m0 = blockIdx.x * 32;
    const int b  = blockIdx.y;

    // Load Q tile [32][64] from theta (= Y cols 0..63)
    {
        int r = tid >> 3, c0 = (tid & 7) * 8;
        const uint2* src = (const uint2*)&g_Y[(size_t)(b * HW + m0 + r) * NPROJ + c0];
        uint2* dst = (uint2*)&Qs[r * 72 + c0];
        dst[0] = src[0]; dst[1] = src[1];
    }

    // ---------------- Phase 1: S = Q @ phi^T into Ss ----------------
    for (int k0 = 0; k0 < HWP; k0 += 128) {
        __syncthreads();
        {
            int kk = tid >> 1, c0 = (tid & 1) * 32;
            const uint2* src = (const uint2*)&g_KV[(size_t)(b * HWP + k0 + kk) * NKV + c0];
            uint2* dst = (uint2*)&Ks[kk * 72 + c0];
            #pragma unroll
            for (int i = 0; i < 8; i++) dst[i] = src[i];
        }
        __syncthreads();

        float sacc[2][2][4];
        #pragma unroll
        for (int mi = 0; mi < 2; mi++)
            #pragma unroll
            for (int ni = 0; ni < 2; ni++)
                #pragma unroll
                for (int j = 0; j < 4; j++) sacc[mi][ni][j] = 0.f;

        #pragma unroll
        for (int k16 = 0; k16 < 64; k16 += 16) {
            unsigned a[2][4], bf[2][2];
            #pragma unroll
            for (int mi = 0; mi < 2; mi++) {
                int r = mi * 16 + g;
                a[mi][0] = *(const unsigned*)&Qs[r * 72 + k16 + 2*t];
                a[mi][1] = *(const unsigned*)&Qs[(r + 8) * 72 + k16 + 2*t];
                a[mi][2] = *(const unsigned*)&Qs[r * 72 + k16 + 2*t + 8];
                a[mi][3] = *(const unsigned*)&Qs[(r + 8) * 72 + k16 + 2*t + 8];
            }
            #pragma unroll
            for (int ni = 0; ni < 2; ni++) {
                int n = warp * 16 + ni * 8 + g;
                bf[ni][0] = *(const unsigned*)&Ks[n * 72 + k16 + 2*t];
                bf[ni][1] = *(const unsigned*)&Ks[n * 72 + k16 + 2*t + 8];
            }
            #pragma unroll
            for (int mi = 0; mi < 2; mi++)
                #pragma unroll
                for (int ni = 0; ni < 2; ni++)
                    mma16816(sacc[mi][ni], a[mi], bf[ni]);
        }
        // store logits
        #pragma unroll
        for (int mi = 0; mi < 2; mi++)
            #pragma unroll
            for (int ni = 0; ni < 2; ni++) {
                int r = mi * 16 + g;
                int col = k0 + warp * 16 + ni * 8 + 2 * t;
                Ss[r * 1028 + col]           = sacc[mi][ni][0];
                Ss[r * 1028 + col + 1]       = sacc[mi][ni][1];
                Ss[(r + 8) * 1028 + col]     = sacc[mi][ni][2];
                Ss[(r + 8) * 1028 + col + 1] = sacc[mi][ni][3];
            }
    }
    __syncthreads();

    // ---------------- Phase 2: softmax rows -> Ps (bf16) ----------------
    #pragma unroll
    for (int rr = 0; rr < 4; rr++) {
        int row = warp * 4 + rr;
        float mx = -1e30f;
        for (int c = lane; c < HWP; c += 32) mx = fmaxf(mx, Ss[row * 1028 + c]);
        #pragma unroll
        for (int o = 16; o; o >>= 1) mx = fmaxf(mx, __shfl_xor_sync(0xffffffffu, mx, o));
        float sum = 0.f;
        for (int c = lane; c < HWP; c += 32) {
            float e = __expf(Ss[row * 1028 + c] - mx);
            sum += e;
            Ps[row * 1032 + c] = __float2bfloat16(e);
        }
        #pragma unroll
        for (int o = 16; o; o >>= 1) sum += __shfl_xor_sync(0xffffffffu, sum, o);
        float inv = 1.f / sum;
        for (int c = lane; c < HWP; c += 32)
            Ps[row * 1032 + c] =
                __float2bfloat16(__bfloat162float(Ps[row * 1032 + c]) * inv);
    }

    // ---------------- Phase 3: O = P @ V (V chunk transposed into Ss region) --
    float oacc[2][4][4];
    #pragma unroll
    for (int mi = 0; mi < 2; mi++)
        #pragma unroll
        for (int ni = 0; ni < 4; ni++)
            #pragma unroll
            for (int j = 0; j < 4; j++) oacc[mi][ni][j] = 0.f;

    for (int k0 = 0; k0 < HWP; k0 += 128) {
        __syncthreads();   // prev mma done (and phase 2 done on first iter)
        // Vs[v][kk] = g[k0+kk][v]  (transpose on store)
        #pragma unroll 4
        for (int kk = 0; kk < 128; kk++)
            Vs[tid * 136 + kk] = g_KV[(size_t)(b * HWP + k0 + kk) * NKV + 64 + tid];
        __syncthreads();

        #pragma unroll
        for (int k16 = 0; k16 < 128; k16 += 16) {
            unsigned a[2][4];
            #pragma unroll
            for (int mi = 0; mi < 2; mi++) {
                int r = mi * 16 + g;
                int cb = k0 + k16 + 2 * t;
                a[mi][0] = *(const unsigned*)&Ps[r * 1032 + cb];
                a[mi][1] = *(const unsigned*)&Ps[(r + 8) * 1032 + cb];
                a[mi][2] = *(const unsigned*)&Ps[r * 1032 + cb + 8];
                a[mi][3] = *(const unsigned*)&Ps[(r + 8) * 1032 + cb + 8];
            }
            #pragma unroll
            for (int ni = 0; ni < 4; ni++) {
                int n = warp * 32 + ni * 8 + g;
                unsigned bf[2];
                bf[0] = *(const unsigned*)&Vs[n * 136 + k16 + 2*t];
                bf[1] = *(const unsigned*)&Vs[n * 136 + k16 + 2*t + 8];
                mma16816(oacc[0][ni], a[0], bf);
                mma16816(oacc[1][ni], a[1], bf);
            }
        }
    }

    // Epilogue -> g_O bf16 [32768,256]
    #pragma unroll
    for (int mi = 0; mi < 2; mi++)
        #pragma unroll
        for (int ni = 0; ni < 4; ni++) {
            int row = b * HW + m0 + mi * 16 + g;
            int col = warp * 32 + ni * 8 + 2 * t;
            *(__nv_bfloat162*)&g_O[(size_t)row * CV + col] =
                __floats2bfloat162_rn(oacc[mi][ni][0], oacc[mi][ni][1]);
            *(__nv_bfloat162*)&g_O[(size_t)(row + 8) * CV + col] =
                __floats2bfloat162_rn(oacc[mi][ni][2], oacc[mi][ni][3]);
        }
}

// ===========================================================================
// K4: out = x + gamma * (O[32768,256] @ w_o[256,512])
// Same tiling as K1: CTA 128x64, K-chunk 32.
// ===========================================================================
__global__ __launch_bounds__(256) void out_kernel(
    const float* __restrict__ x,
    const float* __restrict__ w_o,
    const float* __restrict__ gamma,
    float* __restrict__ out)
{
    __shared__ __nv_bfloat16 As[128][40];
    __shared__ __nv_bfloat16 Bs[64][40];

    const int m0 = blockIdx.y * 128;
    const int n0 = blockIdx.x * 64;

    const int tid  = threadIdx.x;
    const int warp = tid >> 5, lane = tid & 31;
    const int wm = warp >> 1, wn = warp & 1;
    const int g = lane >> 2, t = lane & 3;

    float acc[2][4][4];
    #pragma unroll
    for (int mi = 0; mi < 2; mi++)
        #pragma unroll
        for (int ni = 0; ni < 4; ni++)
            #pragma unroll
            for (int j = 0; j < 4; j++) acc[mi][ni][j] = 0.f;

    const int ra = tid >> 1;            // 0..127
    const int ca = (tid & 1) * 16;      // 0 or 16
    const int ib = tid & 63;
    const int kb = (tid >> 6) * 8;

    for (int kc = 0; kc < CV; kc += 32) {
        {
            const uint4* src = (const uint4*)&g_O[(size_t)(m0 + ra) * CV + kc + ca];
            uint4* dst = (uint4*)&As[ra][ca];
            dst[0] = src[0]; dst[1] = src[1];
        }
        #pragma unroll
        for (int kk = 0; kk < 8; kk++)
            Bs[ib][kb + kk] = __float2bfloat16(w_o[(size_t)(kc + kb + kk) * C_IN + n0 + ib]);
        __syncthreads();

        #pragma unroll
        for (int k16 = 0; k16 < 32; k16 += 16) {
            unsigned a[2][4], bf[4][2];
            #pragma unroll
            for (int mi = 0; mi < 2; mi++) {
                int r = wm * 32 + mi * 16 + g;
                a[mi][0] = *(const unsigned*)&As[r    ][k16 + 2*t    ];
                a[mi][1] = *(const unsigned*)&As[r + 8][k16 + 2*t    ];
                a[mi][2] = *(const unsigned*)&As[r    ][k16 + 2*t + 8];
                a[mi][3] = *(const unsigned*)&As[r + 8][k16 + 2*t + 8];
            }
            #pragma unroll
            for (int ni = 0; ni < 4; ni++) {
                int n = wn * 32 + ni * 8 + g;
                bf[ni][0] = *(const unsigned*)&Bs[n][k16 + 2*t    ];
                bf[ni][1] = *(const unsigned*)&Bs[n][k16 + 2*t + 8];
            }
            #pragma unroll
            for (int mi = 0; mi < 2; mi++)
                #pragma unroll
                for (int ni = 0; ni < 4; ni++)
                    mma16816(acc[mi][ni], a[mi], bf[ni]);
        }
        __syncthreads();
    }

    const float gam = gamma[0];
    #pragma unroll
    for (int mi = 0; mi < 2; mi++)
        #pragma unroll
        for (int ni = 0; ni < 4; ni++) {
            int row = m0 + wm * 32 + mi * 16 + g;
            int col = n0 + wn * 32 + ni * 8 + 2 * t;
            {
                float2 xv = *(const float2*)&x[(size_t)row * C_IN + col];
                float2 ov;
                ov.x = xv.x + gam * acc[mi][ni][0];
                ov.y = xv.y + gam * acc[mi][ni][1];
                *(float2*)&out[(size_t)row * C_IN + col] = ov;
            }
            {
                float2 xv = *(const float2*)&x[(size_t)(row + 8) * C_IN + col];
                float2 ov;
                ov.x = xv.x + gam * acc[mi][ni][2];
                ov.y = xv.y + gam * acc[mi][ni][3];
                *(float2*)&out[(size_t)(row + 8) * C_IN + col] = ov;
            }
        }
}

// ===========================================================================
extern "C" void kernel_launch(void* const* d_in, const int* in_sizes, int n_in,
                              void* d_out, int out_size)
{
    const float* x       = (const float*)d_in[0];
    const float* w_theta = (const float*)d_in[1];
    const float* w_phi   = (const float*)d_in[2];
    const float* w_g     = (const float*)d_in[3];
    const float* w_o     = (const float*)d_in[4];
    const float* gamma   = (const float*)d_in[5];
    float* out = (float*)d_out;

    (void)in_sizes; (void)n_in; (void)out_size;

    // K1: projections
    proj_kernel<<<dim3(NPROJ / 64, M_TOT / 128), 256>>>(x, w_theta, w_phi, w_g);

    // K2: 2x2 maxpool
    {
        int total = 8 * HWP * NKV;
        pool_kernel<<<(total + 255) / 256, 256>>>();
    }

    // K3: fused attention (opt-in smem; attribute set is idempotent & capture-safe)
    cudaFuncSetAttribute(attn_kernel, cudaFuncAttributeMaxDynamicSharedMemorySize, ATTN_SMEM);
    attn_kernel<<<dim3(HW / 32, 8), 256, ATTN_SMEM>>>();

    // K4: output projection + residual
    out_kernel<<<dim3(C_IN / 64, M_TOT / 128), 256>>>(x, w_o, gamma, out);
}

// round 5
// speedup vs baseline: 2.2484x; 2.2484x over previous
#include <cuda_runtime.h>
#include <cuda_bf16.h>
#include <cstdint>

// x: [8,64,64,512] f32; w_theta [512,64]; w_phi [512,64]; w_g [512,256]; w_o [256,512]; gamma [1]
#define M_TOT   32768
#define C_IN    512
#define CK      64
#define CV      256
#define NPROJ   384
#define HW      4096
#define HWP     1024

// -------------------- scratch (device globals) --------------------
__device__ __nv_bfloat16 g_WcatT[(size_t)NPROJ * C_IN];   // [384][512]  W^T (theta|phi|g)
__device__ __nv_bfloat16 g_WoT[(size_t)C_IN * CV];        // [512][256]  w_o^T
__device__ __nv_bfloat16 g_Y[(size_t)M_TOT * NPROJ];      // proj outputs
__device__ __nv_bfloat16 g_phiP[(size_t)8 * HWP * CK];    // pooled phi [b][p][ck]
__device__ __nv_bfloat16 g_vT[(size_t)8 * CV * HWP];      // pooled g, transposed [b][v][p]
__device__ __nv_bfloat16 g_P[(size_t)8 * HW * HWP];       // softmax probs
__device__ __nv_bfloat16 g_O[(size_t)M_TOT * CV];         // attn output

// ---------------------------------------------------------------------------
// mma.sync m16n8k16 bf16 row.col f32
// A frag: a0=(m=g,k=2t) a1=(m+8) a2=(k+8) a3=(m+8,k+8); B frag: Bs[n][k] pairs
// ---------------------------------------------------------------------------
__device__ __forceinline__ void mma16816(float* d, const unsigned* a, const unsigned* b) {
    asm volatile(
        "mma.sync.aligned.m16n8k16.row.col.f32.bf16.bf16.f32 "
        "{%0,%1,%2,%3}, {%4,%5,%6,%7}, {%8,%9}, {%0,%1,%2,%3};\n"
        : "+f"(d[0]), "+f"(d[1]), "+f"(d[2]), "+f"(d[3])
        : "r"(a[0]), "r"(a[1]), "r"(a[2]), "r"(a[3]), "r"(b[0]), "r"(b[1]));
}

__device__ __forceinline__ unsigned packbf2(float x, float y) {
    __nv_bfloat162 h = __floats2bfloat162_rn(x, y);
    return *(unsigned*)&h;
}

// Shared 128x128 compute step: one K=32 chunk. As/Bs are [128][40] bf16.
__device__ __forceinline__ void gemm_chunk(
    const __nv_bfloat16* __restrict__ As, const __nv_bfloat16* __restrict__ Bs,
    int wm, int wn, int g, int t, float acc[4][4][4])
{
    #pragma unroll
    for (int k16 = 0; k16 < 32; k16 += 16) {
        unsigned a[4][4], bb[4][2];
        #pragma unroll
        for (int mi = 0; mi < 4; mi++) {
            const __nv_bfloat16* p0 = As + (wm * 64 + mi * 16 + g) * 40 + k16 + 2 * t;
            a[mi][0] = *(const unsigned*)p0;
            a[mi][1] = *(const unsigned*)(p0 + 8 * 40);
            a[mi][2] = *(const unsigned*)(p0 + 8);
            a[mi][3] = *(const unsigned*)(p0 + 8 * 40 + 8);
        }
        #pragma unroll
        for (int ni = 0; ni < 4; ni++) {
            const __nv_bfloat16* p0 = Bs + (wn * 32 + ni * 8 + g) * 40 + k16 + 2 * t;
            bb[ni][0] = *(const unsigned*)p0;
            bb[ni][1] = *(const unsigned*)(p0 + 8);
        }
        #pragma unroll
        for (int mi = 0; mi < 4; mi++)
            #pragma unroll
            for (int ni = 0; ni < 4; ni++)
                mma16816(acc[mi][ni], a[mi], bb[ni]);
    }
}

// ===========================================================================
// K0 prep: weights -> bf16 transposed
// ===========================================================================
__global__ __launch_bounds__(256) void prep_kernel(
    const float* __restrict__ wt, const float* __restrict__ wp,
    const float* __restrict__ wg, const float* __restrict__ wo)
{
    int idx = blockIdx.x * 256 + threadIdx.x;
    if (idx < NPROJ * C_IN) {                       // WcatT[n][k]
        int k = idx & 511, n = idx >> 9;
        float v = (n < 64)  ? wt[k * CK + n]
                : (n < 128) ? wp[k * CK + (n - 64)]
                            : wg[k * CV + (n - 128)];
        g_WcatT[idx] = __float2bfloat16(v);
    } else if (idx < NPROJ * C_IN + C_IN * CV) {    // WoT[n][k] = wo[k][n]
        int i2 = idx - NPROJ * C_IN;
        int k = i2 & 255, n = i2 >> 8;
        g_WoT[i2] = __float2bfloat16(wo[(size_t)k * C_IN + n]);
    }
}

// ===========================================================================
// K1 proj: Y[32768,384] = bf16( X f32 @ WcatT^T ). CTA 128x128, dbl-buffered.
// ===========================================================================
__global__ __launch_bounds__(256, 2) void proj_kernel(const float* __restrict__ x)
{
    __shared__ __nv_bfloat16 As[2][128 * 40];
    __shared__ __nv_bfloat16 Bs[2][128 * 40];

    const int m0 = blockIdx.y * 128, n0 = blockIdx.x * 128;
    const int tid = threadIdx.x, warp = tid >> 5, lane = tid & 31;
    const int wm = warp >> 2, wn = warp & 3, g = lane >> 2, t = lane & 3;
    const int lr = tid >> 1, lc = (tid & 1) * 16;

    float acc[4][4][4];
    #pragma unroll
    for (int mi = 0; mi < 4; mi++)
        #pragma unroll
        for (int ni = 0; ni < 4; ni++)
            #pragma unroll
            for (int j = 0; j < 4; j++) acc[mi][ni][j] = 0.f;

    const float* Arow = x + (size_t)(m0 + lr) * C_IN + lc;
    const __nv_bfloat16* Brow = g_WcatT + (size_t)(n0 + lr) * C_IN + lc;

    float4 fa[4]; uint4 sb0, sb1;
    #pragma unroll
    for (int i = 0; i < 4; i++) fa[i] = *(const float4*)(Arow + i * 4);
    sb0 = *(const uint4*)(Brow); sb1 = *(const uint4*)(Brow + 8);

    {
        unsigned u[8];
        #pragma unroll
        for (int i = 0; i < 4; i++) {
            u[2*i]   = packbf2(fa[i].x, fa[i].y);
            u[2*i+1] = packbf2(fa[i].z, fa[i].w);
        }
        uint4* da = (uint4*)&As[0][lr * 40 + lc];
        da[0] = make_uint4(u[0], u[1], u[2], u[3]);
        da[1] = make_uint4(u[4], u[5], u[6], u[7]);
        *(uint4*)&Bs[0][lr * 40 + lc] = sb0;
        *(uint4*)&Bs[0][lr * 40 + lc + 8] = sb1;
    }
    __syncthreads();

    const int NIT = C_IN / 32;   // 16
    for (int it = 0; it < NIT; it++) {
        if (it + 1 < NIT) {
            int kb = (it + 1) * 32;
            #pragma unroll
            for (int i = 0; i < 4; i++) fa[i] = *(const float4*)(Arow + kb + i * 4);
            sb0 = *(const uint4*)(Brow + kb); sb1 = *(const uint4*)(Brow + kb + 8);
        }
        int p = it & 1;
        gemm_chunk(&As[p][0], &Bs[p][0], wm, wn, g, t, acc);
        if (it + 1 < NIT) {
            int q = p ^ 1;
            unsigned u[8];
            #pragma unroll
            for (int i = 0; i < 4; i++) {
                u[2*i]   = packbf2(fa[i].x, fa[i].y);
                u[2*i+1] = packbf2(fa[i].z, fa[i].w);
            }
            uint4* da = (uint4*)&As[q][lr * 40 + lc];
            da[0] = make_uint4(u[0], u[1], u[2], u[3]);
            da[1] = make_uint4(u[4], u[5], u[6], u[7]);
            *(uint4*)&Bs[q][lr * 40 + lc] = sb0;
            *(uint4*)&Bs[q][lr * 40 + lc + 8] = sb1;
        }
        __syncthreads();
    }

    #pragma unroll
    for (int mi = 0; mi < 4; mi++)
        #pragma unroll
        for (int ni = 0; ni < 4; ni++) {
            int row = m0 + wm * 64 + mi * 16 + g;
            int col = n0 + wn * 32 + ni * 8 + 2 * t;
            *(unsigned*)&g_Y[(size_t)row * NPROJ + col] =
                packbf2(acc[mi][ni][0], acc[mi][ni][1]);
            *(unsigned*)&g_Y[(size_t)(row + 8) * NPROJ + col] =
                packbf2(acc[mi][ni][2], acc[mi][ni][3]);
        }
}

// ===========================================================================
// K2 pool: phi -> g_phiP [b][p][ck];  g -> g_vT [b][v][p] (transposed)
// ===========================================================================
__global__ __launch_bounds__(256) void pool_kernel()
{
    int idx = blockIdx.x * 256 + threadIdx.x;
    const int T1 = 8 * HWP * CK;            // 524288
    const int T2 = 8 * CV * HWP;            // 2097152
    if (idx < T1) {
        int j = idx & 63, pp = (idx >> 6) & 1023, b = idx >> 16;
        int h2 = pp >> 5, w2 = pp & 31;
        size_t base = (size_t)b * HW;
        float m = -1e30f;
        #pragma unroll
        for (int dh = 0; dh < 2; dh++)
            #pragma unroll
            for (int dw = 0; dw < 2; dw++) {
                int p = (2 * h2 + dh) * 64 + 2 * w2 + dw;
                m = fmaxf(m, __bfloat162float(g_Y[(base + p) * NPROJ + 64 + j]));
            }
        g_phiP[idx] = __float2bfloat16(m);
    } else if (idx < T1 + T2) {
        int i2 = idx - T1;
        int pp = i2 & 1023, v = (i2 >> 10) & 255, b = i2 >> 18;
        int h2 = pp >> 5, w2 = pp & 31;
        size_t base = (size_t)b * HW;
        float m = -1e30f;
        #pragma unroll
        for (int dh = 0; dh < 2; dh++)
            #pragma unroll
            for (int dw = 0; dw < 2; dw++) {
                int p = (2 * h2 + dh) * 64 + 2 * w2 + dw;
                m = fmaxf(m, __bfloat162float(g_Y[(base + p) * NPROJ + 128 + v]));
            }
        g_vT[i2] = __float2bfloat16(m);
    }
}

// ===========================================================================
// K3: S = Q @ phi^T (fp32 smem), softmax, write P bf16.
// CTA = (32 queries, batch). Q frags cached in regs; K chunks double-buffered.
// Smem: Qs[32][72] @0 | Ks[2][128][72] @4608 | Ss f32[32][1032] @41472
// ===========================================================================
#define S_SMEM (4608 + 36864 + 132096)   // 173568

__global__ __launch_bounds__(256) void s_softmax_kernel()
{
    extern __shared__ unsigned char sm[];
    __nv_bfloat16* Qs = (__nv_bfloat16*)(sm);
    __nv_bfloat16* Ks = (__nv_bfloat16*)(sm + 4608);
    float*         Ss = (float*)(sm + 41472);

    const int tid = threadIdx.x, warp = tid >> 5, lane = tid & 31;
    const int g = lane >> 2, t = lane & 3;
    const int m0 = blockIdx.x * 32, b = blockIdx.y;

    // Q tile [32][64] from theta (g_Y cols 0..63)
    {
        int r = tid >> 3, c0 = (tid & 7) * 8;
        const uint2* src = (const uint2*)&g_Y[(size_t)(b * HW + m0 + r) * NPROJ + c0];
        uint2* dst = (uint2*)&Qs[r * 72 + c0];
        dst[0] = src[0]; dst[1] = src[1];
    }

    // K chunk staging: 128 rows x 64ch, tid>>1 = row, (tid&1)*32 = col base
    const int kr = tid >> 1, kc = (tid & 1) * 32;
    const __nv_bfloat16* Ksrc = g_phiP + ((size_t)b * HWP + kr) * CK + kc;
    uint4 st[4];
    #pragma unroll
    for (int i = 0; i < 4; i++) st[i] = *(const uint4*)(Ksrc + i * 8);
    {
        uint4* d = (uint4*)&Ks[kr * 72 + kc];
        #pragma unroll
        for (int i = 0; i < 4; i++) d[i] = st[i];
    }
    __syncthreads();

    // Q fragments (all 4 k16 steps) cached in regs
    unsigned qa[2][4][4];
    #pragma unroll
    for (int mi = 0; mi < 2; mi++)
        #pragma unroll
        for (int kk = 0; kk < 4; kk++) {
            const __nv_bfloat16* p0 = Qs + (mi * 16 + g) * 72 + kk * 16 + 2 * t;
            qa[mi][kk][0] = *(const unsigned*)p0;
            qa[mi][kk][1] = *(const unsigned*)(p0 + 8 * 72);
            qa[mi][kk][2] = *(const unsigned*)(p0 + 8);
            qa[mi][kk][3] = *(const unsigned*)(p0 + 8 * 72 + 8);
        }

    for (int ch = 0; ch < 8; ch++) {
        if (ch + 1 < 8) {
            const __nv_bfloat16* src = Ksrc + (size_t)(ch + 1) * 128 * CK;
            #pragma unroll
            for (int i = 0; i < 4; i++) st[i] = *(const uint4*)(src + i * 8);
        }
        int p = ch & 1;
        const __nv_bfloat16* Kb = Ks + p * (128 * 72);
        #pragma unroll
        for (int ni = 0; ni < 2; ni++) {
            int n = warp * 16 + ni * 8 + g;
            unsigned bfr[4][2];
            #pragma unroll
            for (int kk = 0; kk < 4; kk++) {
                const __nv_bfloat16* p0 = Kb + n * 72 + kk * 16 + 2 * t;
                bfr[kk][0] = *(const unsigned*)p0;
                bfr[kk][1] = *(const unsigned*)(p0 + 8);
            }
            float s0[4] = {0, 0, 0, 0}, s1[4] = {0, 0, 0, 0};
            #pragma unroll
            for (int kk = 0; kk < 4; kk++) {
                mma16816(s0, qa[0][kk], bfr[kk]);
                mma16816(s1, qa[1][kk], bfr[kk]);
            }
            int col = ch * 128 + warp * 16 + ni * 8 + 2 * t;
            Ss[g * 1032 + col]            = s0[0];
            Ss[g * 1032 + col + 1]        = s0[1];
            Ss[(g + 8) * 1032 + col]      = s0[2];
            Ss[(g + 8) * 1032 + col + 1]  = s0[3];
            Ss[(16 + g) * 1032 + col]     = s1[0];
            Ss[(16 + g) * 1032 + col + 1] = s1[1];
            Ss[(24 + g) * 1032 + col]     = s1[2];
            Ss[(24 + g) * 1032 + col + 1] = s1[3];
        }
        if (ch + 1 < 8) {
            uint4* d = (uint4*)&Ks[(p ^ 1) * (128 * 72) + kr * 72 + kc];
            #pragma unroll
            for (int i = 0; i < 4; i++) d[i] = st[i];
        }
        __syncthreads();
    }

    // softmax: warp handles rows warp*4 .. warp*4+3
    #pragma unroll
    for (int rr = 0; rr < 4; rr++) {
        int row = warp * 4 + rr;
        float* srow = Ss + row * 1032;
        float mx = -1e30f;
        for (int c = lane; c < HWP; c += 32) mx = fmaxf(mx, srow[c]);
        #pragma unroll
        for (int o = 16; o; o >>= 1) mx = fmaxf(mx, __shfl_xor_sync(0xffffffffu, mx, o));
        float sum = 0.f;
        for (int c = lane; c < HWP; c += 32) {
            float e = __expf(srow[c] - mx);
            srow[c] = e;
            sum += e;
        }
        #pragma unroll
        for (int o = 16; o; o >>= 1) sum += __shfl_xor_sync(0xffffffffu, sum, o);
        float inv = 1.f / sum;
        size_t orow = (size_t)(b * HW + m0 + row) * HWP;
        for (int c0 = lane * 4; c0 < HWP; c0 += 128) {
            float4 v = *(const float4*)&srow[c0];
            uint2 o2;
            o2.x = packbf2(v.x * inv, v.y * inv);
            o2.y = packbf2(v.z * inv, v.w * inv);
            *(uint2*)&g_P[orow + c0] = o2;
        }
    }
}

// ===========================================================================
// K4 PV: O[b][4096,256] = P[b] @ V[b].  A=g_P (ld 1024), B=g_vT (ld 1024).
// ===========================================================================
__global__ __launch_bounds__(256, 2) void pv_kernel()
{
    __shared__ __nv_bfloat16 As[2][128 * 40];
    __shared__ __nv_bfloat16 Bs[2][128 * 40];

    const int b = blockIdx.z, m0 = blockIdx.y * 128, n0 = blockIdx.x * 128;
    const int tid = threadIdx.x, warp = tid >> 5, lane = tid & 31;
    const int wm = warp >> 2, wn = warp & 3, g = lane >> 2, t = lane & 3;
    const int lr = tid >> 1, lc = (tid & 1) * 16;

    float acc[4][4][4];
    #pragma unroll
    for (int mi = 0; mi < 4; mi++)
        #pragma unroll
        for (int ni = 0; ni < 4; ni++)
            #pragma unroll
            for (int j = 0; j < 4; j++) acc[mi][ni][j] = 0.f;

    const __nv_bfloat16* Arow = g_P  + (size_t)b * HW * HWP + (size_t)(m0 + lr) * HWP + lc;
    const __nv_bfloat16* Brow = g_vT + (size_t)b * CV * HWP + (size_t)(n0 + lr) * HWP + lc;

    uint4 sa0, sa1, sb0, sb1;
    sa0 = *(const uint4*)(Arow);     sa1 = *(const uint4*)(Arow + 8);
    sb0 = *(const uint4*)(Brow);     sb1 = *(const uint4*)(Brow + 8);
    *(uint4*)&As[0][lr * 40 + lc] = sa0;  *(uint4*)&As[0][lr * 40 + lc + 8] = sa1;
    *(uint4*)&Bs[0][lr * 40 + lc] = sb0;  *(uint4*)&Bs[0][lr * 40 + lc + 8] = sb1;
    __syncthreads();

    const int NIT = HWP / 32;   // 32
    for (int it = 0; it < NIT; it++) {
        if (it + 1 < NIT) {
            int kb = (it + 1) * 32;
            sa0 = *(const uint4*)(Arow + kb);  sa1 = *(const uint4*)(Arow + kb + 8);
            sb0 = *(const uint4*)(Brow + kb);  sb1 = *(const uint4*)(Brow + kb + 8);
        }
        int p = it & 1;
        gemm_chunk(&As[p][0], &Bs[p][0], wm, wn, g, t, acc);
        if (it + 1 < NIT) {
            int q = p ^ 1;
            *(uint4*)&As[q][lr * 40 + lc] = sa0;  *(uint4*)&As[q][lr * 40 + lc + 8] = sa1;
            *(uint4*)&Bs[q][lr * 40 + lc] = sb0;  *(uint4*)&Bs[q][lr * 40 + lc + 8] = sb1;
        }
        __syncthreads();
    }

    #pragma unroll
    for (int mi = 0; mi < 4; mi++)
        #pragma unroll
        for (int ni = 0; ni < 4; ni++) {
            int row = b * HW + m0 + wm * 64 + mi * 16 + g;
            int col = n0 + wn * 32 + ni * 8 + 2 * t;
            *(unsigned*)&g_O[(size_t)row * CV + col] =
                packbf2(acc[mi][ni][0], acc[mi][ni][1]);
            *(unsigned*)&g_O[(size_t)(row + 8) * CV + col] =
                packbf2(acc[mi][ni][2], acc[mi][ni][3]);
        }
}

// ===========================================================================
// K5 out: out = x + gamma * (g_O @ w_o).  A=g_O (ld 256), B=g_WoT (ld 256).
// ===========================================================================
__global__ __launch_bounds__(256, 2) void out_kernel(
    const float* __restrict__ x, const float* __restrict__ gamma,
    float* __restrict__ out)
{
    __shared__ __nv_bfloat16 As[2][128 * 40];
    __shared__ __nv_bfloat16 Bs[2][128 * 40];

    const int m0 = blockIdx.y * 128, n0 = blockIdx.x * 128;
    const int tid = threadIdx.x, warp = tid >> 5, lane = tid & 31;
    const int wm = warp >> 2, wn = warp & 3, g = lane >> 2, t = lane & 3;
    const int lr = tid >> 1, lc = (tid & 1) * 16;

    float acc[4][4][4];
    #pragma unroll
    for (int mi = 0; mi < 4; mi++)
        #pragma unroll
        for (int ni = 0; ni < 4; ni++)
            #pragma unroll
            for (int j = 0; j < 4; j++) acc[mi][ni][j] = 0.f;

    const __nv_bfloat16* Arow = g_O   + (size_t)(m0 + lr) * CV + lc;
    const __nv_bfloat16* Brow = g_WoT + (size_t)(n0 + lr) * CV + lc;

    uint4 sa0, sa1, sb0, sb1;
    sa0 = *(const uint4*)(Arow);     sa1 = *(const uint4*)(Arow + 8);
    sb0 = *(const uint4*)(Brow);     sb1 = *(const uint4*)(Brow + 8);
    *(uint4*)&As[0][lr * 40 + lc] = sa0;  *(uint4*)&As[0][lr * 40 + lc + 8] = sa1;
    *(uint4*)&Bs[0][lr * 40 + lc] = sb0;  *(uint4*)&Bs[0][lr * 40 + lc + 8] = sb1;
    __syncthreads();

    const int NIT = CV / 32;   // 8
    for (int it = 0; it < NIT; it++) {
        if (it + 1 < NIT) {
            int kb = (it + 1) * 32;
            sa0 = *(const uint4*)(Arow + kb);  sa1 = *(const uint4*)(Arow + kb + 8);
            sb0 = *(const uint4*)(Brow + kb);  sb1 = *(const uint4*)(Brow + kb + 8);
        }
        int p = it & 1;
        gemm_chunk(&As[p][0], &Bs[p][0], wm, wn, g, t, acc);
        if (it + 1 < NIT) {
            int q = p ^ 1;
            *(uint4*)&As[q][lr * 40 + lc] = sa0;  *(uint4*)&As[q][lr * 40 + lc + 8] = sa1;
            *(uint4*)&Bs[q][lr * 40 + lc] = sb0;  *(uint4*)&Bs[q][lr * 40 + lc + 8] = sb1;
        }
        __syncthreads();
    }

    const float gam = gamma[0];
    #pragma unroll
    for (int mi = 0; mi < 4; mi++)
        #pragma unroll
        for (int ni = 0; ni < 4; ni++) {
            int row = m0 + wm * 64 + mi * 16 + g;
            int col = n0 + wn * 32 + ni * 8 + 2 * t;
            {
                float2 xv = *(const float2*)&x[(size_t)row * C_IN + col];
                float2 ov = make_float2(xv.x + gam * acc[mi][ni][0],
                                        xv.y + gam * acc[mi][ni][1]);
                *(float2*)&out[(size_t)row * C_IN + col] = ov;
            }
            {
                float2 xv = *(const float2*)&x[(size_t)(row + 8) * C_IN + col];
                float2 ov = make_float2(xv.x + gam * acc[mi][ni][2],
                                        xv.y + gam * acc[mi][ni][3]);
                *(float2*)&out[(size_t)(row + 8) * C_IN + col] = ov;
            }
        }
}

// ===========================================================================
extern "C" void kernel_launch(void* const* d_in, const int* in_sizes, int n_in,
                              void* d_out, int out_size)
{
    const float* x       = (const float*)d_in[0];
    const float* w_theta = (const float*)d_in[1];
    const float* w_phi   = (const float*)d_in[2];
    const float* w_g     = (const float*)d_in[3];
    const float* w_o     = (const float*)d_in[4];
    const float* gamma   = (const float*)d_in[5];
    float* out = (float*)d_out;
    (void)in_sizes; (void)n_in; (void)out_size;

    // K0: weight transpose/convert
    {
        int total = NPROJ * C_IN + C_IN * CV;   // 327680
        prep_kernel<<<(total + 255) / 256, 256>>>(w_theta, w_phi, w_g, w_o);
    }
    // K1: projections  [32768,384]
    proj_kernel<<<dim3(NPROJ / 128, M_TOT / 128), 256>>>(x);
    // K2: pooling (phi row-major, g transposed)
    {
        int total = 8 * HWP * CK + 8 * CV * HWP;   // 2621440
        pool_kernel<<<(total + 255) / 256, 256>>>();
    }
    // K3: S + softmax -> P
    cudaFuncSetAttribute(s_softmax_kernel, cudaFuncAttributeMaxDynamicSharedMemorySize, S_SMEM);
    s_softmax_kernel<<<dim3(HW / 32, 8), 256, S_SMEM>>>();
    // K4: P @ V
    pv_kernel<<<dim3(CV / 128, HW / 128, 8), 256>>>();
    // K5: output projection + residual
    out_kernel<<<dim3(C_IN / 128, M_TOT / 128), 256>>>(x, gamma, out);
}

// round 8
// speedup vs baseline: 2.3679x; 1.0531x over previous
#include <cuda_runtime.h>
#include <cuda_bf16.h>
#include <cstdint>

// x: [8,64,64,512] f32; w_theta [512,64]; w_phi [512,64]; w_g [512,256]; w_o [256,512]; gamma [1]
#define M_TOT   32768
#define C_IN    512
#define CK      64
#define CV      256
#define NPROJ   384
#define HW      4096
#define HWP     1024

// -------------------- scratch (device globals) --------------------
__device__ __nv_bfloat16 g_WcatT[(size_t)NPROJ * C_IN];   // [384][512]  W^T (theta|phi|g)
__device__ __nv_bfloat16 g_WoT[(size_t)C_IN * CV];        // [512][256]  w_o^T
__device__ __nv_bfloat16 g_Y[(size_t)M_TOT * NPROJ];      // proj outputs
__device__ __nv_bfloat16 g_phiP[(size_t)8 * HWP * CK];    // pooled phi [b][p][ck]
__device__ __nv_bfloat16 g_vT[(size_t)8 * CV * HWP];      // pooled g, transposed [b][v][p]
__device__ __nv_bfloat16 g_P[(size_t)8 * HW * HWP];       // softmax probs
__device__ __nv_bfloat16 g_O[(size_t)M_TOT * CV];         // attn output

// ---------------------------------------------------------------------------
__device__ __forceinline__ uint32_t smem_u32(const void* p) {
    uint32_t a;
    asm("{ .reg .u64 t; cvta.to.shared.u64 t, %1; cvt.u32.u64 %0, t; }" : "=r"(a) : "l"(p));
    return a;
}

// mma.sync m16n8k16 bf16 row.col f32
__device__ __forceinline__ void mma16816(float* d, const unsigned* a, const unsigned* b) {
    asm volatile(
        "mma.sync.aligned.m16n8k16.row.col.f32.bf16.bf16.f32 "
        "{%0,%1,%2,%3}, {%4,%5,%6,%7}, {%8,%9}, {%0,%1,%2,%3};\n"
        : "+f"(d[0]), "+f"(d[1]), "+f"(d[2]), "+f"(d[3])
        : "r"(a[0]), "r"(a[1]), "r"(a[2]), "r"(a[3]), "r"(b[0]), "r"(b[1]));
}

// ldmatrix x4 (non-transposed): 4 x 8x8 b16 matrices; lane L of group g supplies
// the address of that matrix's row; destination reg g gets frag in mma layout.
__device__ __forceinline__ void ldsm4(unsigned r[4], uint32_t addr) {
    asm volatile("ldmatrix.sync.aligned.m8n8.x4.shared.b16 {%0,%1,%2,%3}, [%4];"
                 : "=r"(r[0]), "=r"(r[1]), "=r"(r[2]), "=r"(r[3]) : "r"(addr));
}

__device__ __forceinline__ unsigned packbf2(float x, float y) {
    __nv_bfloat162 h = __floats2bfloat162_rn(x, y);
    return *(unsigned*)&h;
}

// ---------------------------------------------------------------------------
// 128x128 CTA GEMM chunk (K=32) via ldmatrix. Tiles are [128][40] bf16 (80B rows).
// aBase: lane-resolved A addr = As + (wm*64 + (lane&15))*80 + ((lane>>4)*8)*2
// bBase: lane-resolved B addr = Bs + (wn*32 + (lane&7) + ((lane&16)?8:0))*80
//                                  + ((lane&8)?8:0)*2
// A x4 subs -> a0(m,k) a1(m+8,k) a2(m,k+8) a3(m+8,k+8)  [matches mma A frag]
// B x4 subs -> r0(n0-7,k) r1(n0-7,k+8) r2(n8-15,k) r3(n8-15,k+8)
// ---------------------------------------------------------------------------
__device__ __forceinline__ void gemm_chunk(uint32_t aBase, uint32_t bBase, float acc[4][4][4])
{
    #pragma unroll
    for (int k16 = 0; k16 < 32; k16 += 16) {
        unsigned a[4][4], bb[2][4];
        #pragma unroll
        for (int mi = 0; mi < 4; mi++) ldsm4(a[mi], aBase + mi * 16 * 80 + k16 * 2);
        #pragma unroll
        for (int np = 0; np < 2; np++) ldsm4(bb[np], bBase + np * 16 * 80 + k16 * 2);
        #pragma unroll
        for (int mi = 0; mi < 4; mi++) {
            mma16816(acc[mi][0], a[mi], &bb[0][0]);
            mma16816(acc[mi][1], a[mi], &bb[0][2]);
            mma16816(acc[mi][2], a[mi], &bb[1][0]);
            mma16816(acc[mi][3], a[mi], &bb[1][2]);
        }
    }
}

// lane-resolved base offsets (bytes) into a [128][40] bf16 tile
__device__ __forceinline__ uint32_t a_lane_off(int wm, int lane) {
    return (uint32_t)((wm * 64 + (lane & 15)) * 80 + ((lane >> 4) << 4));
}
__device__ __forceinline__ uint32_t b_lane_off(int wn, int lane) {
    return (uint32_t)((wn * 32 + (lane & 7) + ((lane & 16) ? 8 : 0)) * 80
                      + ((lane & 8) ? 16 : 0));
}

// ===========================================================================
// K0 prep: weights -> bf16 transposed
// ===========================================================================
__global__ __launch_bounds__(256) void prep_kernel(
    const float* __restrict__ wt, const float* __restrict__ wp,
    const float* __restrict__ wg, const float* __restrict__ wo)
{
    int idx = blockIdx.x * 256 + threadIdx.x;
    if (idx < NPROJ * C_IN) {                       // WcatT[n][k]
        int k = idx & 511, n = idx >> 9;
        float v = (n < 64)  ? wt[k * CK + n]
                : (n < 128) ? wp[k * CK + (n - 64)]
                            : wg[k * CV + (n - 128)];
        g_WcatT[idx] = __float2bfloat16(v);
    } else if (idx < NPROJ * C_IN + C_IN * CV) {    // WoT[n][k] = wo[k][n]
        int i2 = idx - NPROJ * C_IN;
        int k = i2 & 255, n = i2 >> 8;
        g_WoT[i2] = __float2bfloat16(wo[(size_t)k * C_IN + n]);
    }
}

// ===========================================================================
// K1 proj: Y[32768,384] = bf16( X f32 @ WcatT^T ). CTA 128x128, dbl-buffered.
// ===========================================================================
__global__ __launch_bounds__(256, 2) void proj_kernel(const float* __restrict__ x)
{
    __shared__ __nv_bfloat16 As[2][128 * 40];
    __shared__ __nv_bfloat16 Bs[2][128 * 40];

    const int m0 = blockIdx.y * 128, n0 = blockIdx.x * 128;
    const int tid = threadIdx.x, warp = tid >> 5, lane = tid & 31;
    const int wm = warp >> 2, wn = warp & 3, g = lane >> 2, t = lane & 3;
    const int lr = tid >> 1, lc = (tid & 1) * 16;

    const uint32_t As0 = smem_u32(&As[0][0]), Bs0 = smem_u32(&Bs[0][0]);
    const uint32_t aoff = a_lane_off(wm, lane), boff = b_lane_off(wn, lane);
    const uint32_t ASTRIDE = 128 * 80;   // bytes per buffer

    float acc[4][4][4];
    #pragma unroll
    for (int mi = 0; mi < 4; mi++)
        #pragma unroll
        for (int ni = 0; ni < 4; ni++)
            #pragma unroll
            for (int j = 0; j < 4; j++) acc[mi][ni][j] = 0.f;

    const float* Arow = x + (size_t)(m0 + lr) * C_IN + lc;
    const __nv_bfloat16* Brow = g_WcatT + (size_t)(n0 + lr) * C_IN + lc;

    float4 fa[4]; uint4 sb0, sb1;
    #pragma unroll
    for (int i = 0; i < 4; i++) fa[i] = *(const float4*)(Arow + i * 4);
    sb0 = *(const uint4*)(Brow); sb1 = *(const uint4*)(Brow + 8);

    {
        unsigned u[8];
        #pragma unroll
        for (int i = 0; i < 4; i++) {
            u[2*i]   = packbf2(fa[i].x, fa[i].y);
            u[2*i+1] = packbf2(fa[i].z, fa[i].w);
        }
        uint4* da = (uint4*)&As[0][lr * 40 + lc];
        da[0] = make_uint4(u[0], u[1], u[2], u[3]);
        da[1] = make_uint4(u[4], u[5], u[6], u[7]);
        *(uint4*)&Bs[0][lr * 40 + lc] = sb0;
        *(uint4*)&Bs[0][lr * 40 + lc + 8] = sb1;
    }
    __syncthreads();

    const int NIT = C_IN / 32;   // 16
    for (int it = 0; it < NIT; it++) {
        if (it + 1 < NIT) {
            int kb = (it + 1) * 32;
            #pragma unroll
            for (int i = 0; i < 4; i++) fa[i] = *(const float4*)(Arow + kb + i * 4);
            sb0 = *(const uint4*)(Brow + kb); sb1 = *(const uint4*)(Brow + kb + 8);
        }
        int p = it & 1;
        gemm_chunk(As0 + p * ASTRIDE + aoff, Bs0 + p * ASTRIDE + boff, acc);
        if (it + 1 < NIT) {
            int q = p ^ 1;
            unsigned u[8];
            #pragma unroll
            for (int i = 0; i < 4; i++) {
                u[2*i]   = packbf2(fa[i].x, fa[i].y);
                u[2*i+1] = packbf2(fa[i].z, fa[i].w);
            }
            uint4* da = (uint4*)&As[q][lr * 40 + lc];
            da[0] = make_uint4(u[0], u[1], u[2], u[3]);
            da[1] = make_uint4(u[4], u[5], u[6], u[7]);
            *(uint4*)&Bs[q][lr * 40 + lc] = sb0;
            *(uint4*)&Bs[q][lr * 40 + lc + 8] = sb1;
        }
        __syncthreads();
    }

    #pragma unroll
    for (int mi = 0; mi < 4; mi++)
        #pragma unroll
        for (int ni = 0; ni < 4; ni++) {
            int row = m0 + wm * 64 + mi * 16 + g;
            int col = n0 + wn * 32 + ni * 8 + 2 * t;
            *(unsigned*)&g_Y[(size_t)row * NPROJ + col] =
                packbf2(acc[mi][ni][0], acc[mi][ni][1]);
            *(unsigned*)&g_Y[(size_t)(row + 8) * NPROJ + col] =
                packbf2(acc[mi][ni][2], acc[mi][ni][3]);
        }
}

// ===========================================================================
// K2 pool: phi -> g_phiP [b][p][ck];  g -> g_vT [b][v][p] (transposed)
// ===========================================================================
__global__ __launch_bounds__(256) void pool_kernel()
{
    int idx = blockIdx.x * 256 + threadIdx.x;
    const int T1 = 8 * HWP * CK;
    const int T2 = 8 * CV * HWP;
    if (idx < T1) {
        int j = idx & 63, pp = (idx >> 6) & 1023, b = idx >> 16;
        int h2 = pp >> 5, w2 = pp & 31;
        size_t base = (size_t)b * HW;
        float m = -1e30f;
        #pragma unroll
        for (int dh = 0; dh < 2; dh++)
            #pragma unroll
            for (int dw = 0; dw < 2; dw++) {
                int p = (2 * h2 + dh) * 64 + 2 * w2 + dw;
                m = fmaxf(m, __bfloat162float(g_Y[(base + p) * NPROJ + 64 + j]));
            }
        g_phiP[idx] = __float2bfloat16(m);
    } else if (idx < T1 + T2) {
        int i2 = idx - T1;
        int pp = i2 & 1023, v = (i2 >> 10) & 255, b = i2 >> 18;
        int h2 = pp >> 5, w2 = pp & 31;
        size_t base = (size_t)b * HW;
        float m = -1e30f;
        #pragma unroll
        for (int dh = 0; dh < 2; dh++)
            #pragma unroll
            for (int dw = 0; dw < 2; dw++) {
                int p = (2 * h2 + dh) * 64 + 2 * w2 + dw;
                m = fmaxf(m, __bfloat162float(g_Y[(base + p) * NPROJ + 128 + v]));
            }
        g_vT[i2] = __float2bfloat16(m);
    }
}

// ===========================================================================
// K3: S = Q @ phi^T, softmax, write P bf16.  Query tile M=16 -> 2 CTAs/SM.
// Smem: Qs[16][72] @0 | Ks[2][128][72] @2304 | Ss f32[16][1032] @39168
// ===========================================================================
#define S_SMEM (2304 + 36864 + 66048)   // 105216

__global__ __launch_bounds__(256) void s_softmax_kernel()
{
    extern __shared__ unsigned char sm[];
    __nv_bfloat16* Qs = (__nv_bfloat16*)(sm);
    __nv_bfloat16* Ks = (__nv_bfloat16*)(sm + 2304);
    float*         Ss = (float*)(sm + 39168);

    const int tid = threadIdx.x, warp = tid >> 5, lane = tid & 31;
    const int g = lane >> 2, t = lane & 3;
    const int m0 = blockIdx.x * 16, b = blockIdx.y;

    // Q tile [16][64] from theta (g_Y cols 0..63)
    if (tid < 128) {
        int r = tid >> 3, c0 = (tid & 7) * 8;
        const uint2* src = (const uint2*)&g_Y[(size_t)(b * HW + m0 + r) * NPROJ + c0];
        uint2* dst = (uint2*)&Qs[r * 72 + c0];
        dst[0] = src[0]; dst[1] = src[1];
    }

    const int kr = tid >> 1, kc = (tid & 1) * 32;
    const __nv_bfloat16* Ksrc = g_phiP + ((size_t)b * HWP + kr) * CK + kc;
    uint4 st[4];
    #pragma unroll
    for (int i = 0; i < 4; i++) st[i] = *(const uint4*)(Ksrc + i * 8);
    {
        uint4* d = (uint4*)&Ks[kr * 72 + kc];
        #pragma unroll
        for (int i = 0; i < 4; i++) d[i] = st[i];
    }
    __syncthreads();

    // Q fragments for 16 rows, all 4 k16 steps (plain loads; done once)
    unsigned qa[4][4];
    #pragma unroll
    for (int kk = 0; kk < 4; kk++) {
        const __nv_bfloat16* p0 = Qs + g * 72 + kk * 16 + 2 * t;
        qa[kk][0] = *(const unsigned*)p0;
        qa[kk][1] = *(const unsigned*)(p0 + 8 * 72);
        qa[kk][2] = *(const unsigned*)(p0 + 8);
        qa[kk][3] = *(const unsigned*)(p0 + 8 * 72 + 8);
    }

    // ldmatrix lane base within a K tile (row stride 144 B):
    //  per-ni base row = warp*16 + ni*8 + (lane&7); col = 8*(lane>>3) of 32-col span
    const uint32_t Ks_u32 = smem_u32(Ks);
    const uint32_t kslane = (uint32_t)((warp * 16 + (lane & 7)) * 144 + (lane >> 3) * 16);

    for (int ch = 0; ch < 8; ch++) {
        if (ch + 1 < 8) {
            const __nv_bfloat16* src = Ksrc + (size_t)(ch + 1) * 128 * CK;
            #pragma unroll
            for (int i = 0; i < 4; i++) st[i] = *(const uint4*)(src + i * 8);
        }
        int p = ch & 1;
        uint32_t kbase = Ks_u32 + (uint32_t)p * (128 * 144) + kslane;
        #pragma unroll
        for (int ni = 0; ni < 2; ni++) {
            // two x4 loads cover k-cols 0..31 and 32..63 for this 8-row n group
            unsigned b01[4], b23[4];
            ldsm4(b01, kbase + (uint32_t)ni * 8 * 144);
            ldsm4(b23, kbase + (uint32_t)ni * 8 * 144 + 64);
            float s0[4] = {0, 0, 0, 0};
            mma16816(s0, qa[0], &b01[0]);
            mma16816(s0, qa[1], &b01[2]);
            mma16816(s0, qa[2], &b23[0]);
            mma16816(s0, qa[3], &b23[2]);
            int col = ch * 128 + warp * 16 + ni * 8 + 2 * t;
            Ss[g * 1032 + col]           = s0[0];
            Ss[g * 1032 + col + 1]       = s0[1];
            Ss[(g + 8) * 1032 + col]     = s0[2];
            Ss[(g + 8) * 1032 + col + 1] = s0[3];
        }
        if (ch + 1 < 8) {
            uint4* d = (uint4*)&Ks[(p ^ 1) * (128 * 72) + kr * 72 + kc];
            #pragma unroll
            for (int i = 0; i < 4; i++) d[i] = st[i];
        }
        __syncthreads();
    }

    // softmax: warp handles rows warp*2 .. warp*2+1
    #pragma unroll
    for (int rr = 0; rr < 2; rr++) {
        int row = warp * 2 + rr;
        float* srow = Ss + row * 1032;
        float mx = -1e30f;
        for (int c = lane; c < HWP; c += 32) mx = fmaxf(mx, srow[c]);
        #pragma unroll
        for (int o = 16; o; o >>= 1) mx = fmaxf(mx, __shfl_xor_sync(0xffffffffu, mx, o));
        float sum = 0.f;
        for (int c = lane; c < HWP; c += 32) {
            float e = __expf(srow[c] - mx);
            srow[c] = e;
            sum += e;
        }
        #pragma unroll
        for (int o = 16; o; o >>= 1) sum += __shfl_xor_sync(0xffffffffu, sum, o);
        float inv = 1.f / sum;
        size_t orow = (size_t)(b * HW + m0 + row) * HWP;
        for (int c0 = lane * 4; c0 < HWP; c0 += 128) {
            float4 v = *(const float4*)&srow[c0];
            uint2 o2;
            o2.x = packbf2(v.x * inv, v.y * inv);
            o2.y = packbf2(v.z * inv, v.w * inv);
            *(uint2*)&g_P[orow + c0] = o2;
        }
    }
}

// ===========================================================================
// K4 PV: O[b][4096,256] = P[b] @ V[b]^T.  A=g_P (ld 1024), B=g_vT (ld 1024).
// ===========================================================================
__global__ __launch_bounds__(256, 2) void pv_kernel()
{
    __shared__ __nv_bfloat16 As[2][128 * 40];
    __shared__ __nv_bfloat16 Bs[2][128 * 40];

    const int b = blockIdx.z, m0 = blockIdx.y * 128, n0 = blockIdx.x * 128;
    const int tid = threadIdx.x, warp = tid >> 5, lane = tid & 31;
    const int wm = warp >> 2, wn = warp & 3, g = lane >> 2, t = lane & 3;
    const int lr = tid >> 1, lc = (tid & 1) * 16;

    const uint32_t As0 = smem_u32(&As[0][0]), Bs0 = smem_u32(&Bs[0][0]);
    const uint32_t aoff = a_lane_off(wm, lane), boff = b_lane_off(wn, lane);
    const uint32_t ASTRIDE = 128 * 80;

    float acc[4][4][4];
    #pragma unroll
    for (int mi = 0; mi < 4; mi++)
        #pragma unroll
        for (int ni = 0; ni < 4; ni++)
            #pragma unroll
            for (int j = 0; j < 4; j++) acc[mi][ni][j] = 0.f;

    const __nv_bfloat16* Arow = g_P  + (size_t)b * HW * HWP + (size_t)(m0 + lr) * HWP + lc;
    const __nv_bfloat16* Brow = g_vT + (size_t)b * CV * HWP + (size_t)(n0 + lr) * HWP + lc;

    uint4 sa0, sa1, sb0, sb1;
    sa0 = *(const uint4*)(Arow);     sa1 = *(const uint4*)(Arow + 8);
    sb0 = *(const uint4*)(Brow);     sb1 = *(const uint4*)(Brow + 8);
    *(uint4*)&As[0][lr * 40 + lc] = sa0;  *(uint4*)&As[0][lr * 40 + lc + 8] = sa1;
    *(uint4*)&Bs[0][lr * 40 + lc] = sb0;  *(uint4*)&Bs[0][lr * 40 + lc + 8] = sb1;
    __syncthreads();

    const int NIT = HWP / 32;   // 32
    for (int it = 0; it < NIT; it++) {
        if (it + 1 < NIT) {
            int kb = (it + 1) * 32;
            sa0 = *(const uint4*)(Arow + kb);  sa1 = *(const uint4*)(Arow + kb + 8);
            sb0 = *(const uint4*)(Brow + kb);  sb1 = *(const uint4*)(Brow + kb + 8);
        }
        int p = it & 1;
        gemm_chunk(As0 + p * ASTRIDE + aoff, Bs0 + p * ASTRIDE + boff, acc);
        if (it + 1 < NIT) {
            int q = p ^ 1;
            *(uint4*)&As[q][lr * 40 + lc] = sa0;  *(uint4*)&As[q][lr * 40 + lc + 8] = sa1;
            *(uint4*)&Bs[q][lr * 40 + lc] = sb0;  *(uint4*)&Bs[q][lr * 40 + lc + 8] = sb1;
        }
        __syncthreads();
    }

    #pragma unroll
    for (int mi = 0; mi < 4; mi++)
        #pragma unroll
        for (int ni = 0; ni < 4; ni++) {
            int row = b * HW + m0 + wm * 64 + mi * 16 + g;
            int col = n0 + wn * 32 + ni * 8 + 2 * t;
            *(unsigned*)&g_O[(size_t)row * CV + col] =
                packbf2(acc[mi][ni][0], acc[mi][ni][1]);
            *(unsigned*)&g_O[(size_t)(row + 8) * CV + col] =
                packbf2(acc[mi][ni][2], acc[mi][ni][3]);
        }
}

// ===========================================================================
// K5 out: out = x + gamma * (g_O @ w_o).  A=g_O (ld 256), B=g_WoT (ld 256).
// ===========================================================================
__global__ __launch_bounds__(256, 2) void out_kernel(
    const float* __restrict__ x, const float* __restrict__ gamma,
    float* __restrict__ out)
{
    __shared__ __nv_bfloat16 As[2][128 * 40];
    __shared__ __nv_bfloat16 Bs[2][128 * 40];

    const int m0 = blockIdx.y * 128, n0 = blockIdx.x * 128;
    const int tid = threadIdx.x, warp = tid >> 5, lane = tid & 31;
    const int wm = warp >> 2, wn = warp & 3, g = lane >> 2, t = lane & 3;
    const int lr = tid >> 1, lc = (tid & 1) * 16;

    const uint32_t As0 = smem_u32(&As[0][0]), Bs0 = smem_u32(&Bs[0][0]);
    const uint32_t aoff = a_lane_off(wm, lane), boff = b_lane_off(wn, lane);
    const uint32_t ASTRIDE = 128 * 80;

    float acc[4][4][4];
    #pragma unroll
    for (int mi = 0; mi < 4; mi++)
        #pragma unroll
        for (int ni = 0; ni < 4; ni++)
            #pragma unroll
            for (int j = 0; j < 4; j++) acc[mi][ni][j] = 0.f;

    const __nv_bfloat16* Arow = g_O   + (size_t)(m0 + lr) * CV + lc;
    const __nv_bfloat16* Brow = g_WoT + (size_t)(n0 + lr) * CV + lc;

    uint4 sa0, sa1, sb0, sb1;
    sa0 = *(const uint4*)(Arow);     sa1 = *(const uint4*)(Arow + 8);
    sb0 = *(const uint4*)(Brow);     sb1 = *(const uint4*)(Brow + 8);
    *(uint4*)&As[0][lr * 40 + lc] = sa0;  *(uint4*)&As[0][lr * 40 + lc + 8] = sa1;
    *(uint4*)&Bs[0][lr * 40 + lc] = sb0;  *(uint4*)&Bs[0][lr * 40 + lc + 8] = sb1;
    __syncthreads();

    const int NIT = CV / 32;   // 8
    for (int it = 0; it < NIT; it++) {
        if (it + 1 < NIT) {
            int kb = (it + 1) * 32;
            sa0 = *(const uint4*)(Arow + kb);  sa1 = *(const uint4*)(Arow + kb + 8);
            sb0 = *(const uint4*)(Brow + kb);  sb1 = *(const uint4*)(Brow + kb + 8);
        }
        int p = it & 1;
        gemm_chunk(As0 + p * ASTRIDE + aoff, Bs0 + p * ASTRIDE + boff, acc);
        if (it + 1 < NIT) {
            int q = p ^ 1;
            *(uint4*)&As[q][lr * 40 + lc] = sa0;  *(uint4*)&As[q][lr * 40 + lc + 8] = sa1;
            *(uint4*)&Bs[q][lr * 40 + lc] = sb0;  *(uint4*)&Bs[q][lr * 40 + lc + 8] = sb1;
        }
        __syncthreads();
    }

    const float gam = gamma[0];
    #pragma unroll
    for (int mi = 0; mi < 4; mi++)
        #pragma unroll
        for (int ni = 0; ni < 4; ni++) {
            int row = m0 + wm * 64 + mi * 16 + g;
            int col = n0 + wn * 32 + ni * 8 + 2 * t;
            {
                float2 xv = *(const float2*)&x[(size_t)row * C_IN + col];
                float2 ov = make_float2(xv.x + gam * acc[mi][ni][0],
                                        xv.y + gam * acc[mi][ni][1]);
                *(float2*)&out[(size_t)row * C_IN + col] = ov;
            }
            {
                float2 xv = *(const float2*)&x[(size_t)(row + 8) * C_IN + col];
                float2 ov = make_float2(xv.x + gam * acc[mi][ni][2],
                                        xv.y + gam * acc[mi][ni][3]);
                *(float2*)&out[(size_t)(row + 8) * C_IN + col] = ov;
            }
        }
}

// ===========================================================================
extern "C" void kernel_launch(void* const* d_in, const int* in_sizes, int n_in,
                              void* d_out, int out_size)
{
    const float* x       = (const float*)d_in[0];
    const float* w_theta = (const float*)d_in[1];
    const float* w_phi   = (const float*)d_in[2];
    const float* w_g     = (const float*)d_in[3];
    const float* w_o     = (const float*)d_in[4];
    const float* gamma   = (const float*)d_in[5];
    float* out = (float*)d_out;
    (void)in_sizes; (void)n_in; (void)out_size;

    cudaFuncSetAttribute(s_softmax_kernel, cudaFuncAttributeMaxDynamicSharedMemorySize, S_SMEM);

    // K0: weight transpose/convert
    {
        int total = NPROJ * C_IN + C_IN * CV;
        prep_kernel<<<(total + 255) / 256, 256>>>(w_theta, w_phi, w_g, w_o);
    }
    // K1: projections
    proj_kernel<<<dim3(NPROJ / 128, M_TOT / 128), 256>>>(x);
    // K2: pooling (phi row-major, g transposed)
    {
        int total = 8 * HWP * CK + 8 * CV * HWP;
        pool_kernel<<<(total + 255) / 256, 256>>>();
    }
    // K3: S + softmax -> P
    s_softmax_kernel<<<dim3(HW / 16, 8), 256, S_SMEM>>>();
    // K4: P @ V
    pv_kernel<<<dim3(CV / 128, HW / 128, 8), 256>>>();
    // K5: output projection + residual
    out_kernel<<<dim3(C_IN / 128, M_TOT / 128), 256>>>(x, gamma, out);
}

// round 9
// speedup vs baseline: 2.6909x; 1.1364x over previous
#include <cuda_runtime.h>
#include <cuda_bf16.h>
#include <cstdint>

// x: [8,64,64,512] f32; w_theta [512,64]; w_phi [512,64]; w_g [512,256]; w_o [256,512]; gamma [1]
#define M_TOT   32768
#define C_IN    512
#define CK      64
#define CV      256
#define NPROJ   384
#define HW      4096
#define HWP     1024

// -------------------- scratch (device globals) --------------------
__device__ __nv_bfloat16 g_WcatT[(size_t)NPROJ * C_IN];   // [384][512]  W^T (theta|phi|g)
__device__ __nv_bfloat16 g_WoT[(size_t)C_IN * CV];        // [512][256]  w_o^T
__device__ __nv_bfloat16 g_Xbf[(size_t)M_TOT * C_IN];     // x in bf16
__device__ __nv_bfloat16 g_Y[(size_t)M_TOT * NPROJ];      // proj outputs
__device__ __nv_bfloat16 g_phiP[(size_t)8 * HWP * CK];    // pooled phi [b][p][ck]
__device__ __nv_bfloat16 g_vT[(size_t)8 * CV * HWP];      // pooled g, transposed [b][v][p]
__device__ __nv_bfloat16 g_P[(size_t)8 * HW * HWP];       // softmax probs
__device__ __nv_bfloat16 g_O[(size_t)M_TOT * CV];         // attn output

// ---------------------------------------------------------------------------
__device__ __forceinline__ uint32_t smem_u32(const void* p) {
    uint32_t a;
    asm("{ .reg .u64 t; cvta.to.shared.u64 t, %1; cvt.u32.u64 %0, t; }" : "=r"(a) : "l"(p));
    return a;
}
__device__ __forceinline__ void mma16816(float* d, const unsigned* a, const unsigned* b) {
    asm volatile(
        "mma.sync.aligned.m16n8k16.row.col.f32.bf16.bf16.f32 "
        "{%0,%1,%2,%3}, {%4,%5,%6,%7}, {%8,%9}, {%0,%1,%2,%3};\n"
        : "+f"(d[0]), "+f"(d[1]), "+f"(d[2]), "+f"(d[3])
        : "r"(a[0]), "r"(a[1]), "r"(a[2]), "r"(a[3]), "r"(b[0]), "r"(b[1]));
}
__device__ __forceinline__ void ldsm4(unsigned r[4], uint32_t addr) {
    asm volatile("ldmatrix.sync.aligned.m8n8.x4.shared.b16 {%0,%1,%2,%3}, [%4];"
                 : "=r"(r[0]), "=r"(r[1]), "=r"(r[2]), "=r"(r[3]) : "r"(addr));
}
__device__ __forceinline__ void cp16(uint32_t d, const void* g) {
    asm volatile("cp.async.cg.shared.global [%0], [%1], 16;" :: "r"(d), "l"(g));
}
#define CP_COMMIT() asm volatile("cp.async.commit_group;" ::: "memory")
#define CP_WAIT1()  asm volatile("cp.async.wait_group 1;"  ::: "memory")

__device__ __forceinline__ unsigned packbf2(float x, float y) {
    __nv_bfloat162 h = __floats2bfloat162_rn(x, y);
    return *(unsigned*)&h;
}

// ---------------------------------------------------------------------------
// GEMM: 128x128 CTA tile, K-chunk 64, tiles [128][72] bf16 (144 B rows, 9 mod 8
// coprime -> ldmatrix conflict-free). 3-stage cp.async pipeline.
// Stage size = 128*144 = 18432 B; A stages at 0, B stages at 3*18432.
// ---------------------------------------------------------------------------
#define STG     18432
#define GSMEM   (6 * STG)   // 110592

__device__ __forceinline__ uint32_t a_lane_off(int wm, int lane) {
    return (uint32_t)((wm * 64 + (lane & 15)) * 144 + ((lane >> 4) << 4));
}
__device__ __forceinline__ uint32_t b_lane_off(int wn, int lane) {
    return (uint32_t)((wn * 32 + (lane & 7) + ((lane & 16) ? 8 : 0)) * 144
                      + ((lane & 8) ? 16 : 0));
}
__device__ __forceinline__ void issue_stage(uint32_t smA, uint32_t smB, uint32_t cpoff,
    const __nv_bfloat16* ga, const __nv_bfloat16* gb, int s)
{
    uint32_t da = smA + s * STG + cpoff;
    uint32_t db = smB + s * STG + cpoff;
    #pragma unroll
    for (int j = 0; j < 4; j++) {
        cp16(da + j * 16, ga + j * 8);
        cp16(db + j * 16, gb + j * 8);
    }
}
__device__ __forceinline__ void gemm_chunk64(uint32_t aBase, uint32_t bBase, float acc[4][4][4])
{
    #pragma unroll
    for (int k16 = 0; k16 < 4; k16++) {
        unsigned a[4][4], bb[2][4];
        #pragma unroll
        for (int mi = 0; mi < 4; mi++) ldsm4(a[mi], aBase + mi * 16 * 144 + k16 * 32);
        #pragma unroll
        for (int np = 0; np < 2; np++) ldsm4(bb[np], bBase + np * 16 * 144 + k16 * 32);
        #pragma unroll
        for (int mi = 0; mi < 4; mi++) {
            mma16816(acc[mi][0], a[mi], &bb[0][0]);
            mma16816(acc[mi][1], a[mi], &bb[0][2]);
            mma16816(acc[mi][2], a[mi], &bb[1][0]);
            mma16816(acc[mi][3], a[mi], &bb[1][2]);
        }
    }
}

// Shared mainloop body (NIT chunks); Arow_g/Brow_g are per-thread row pointers
// (already offset by (tid>>1) row and (tid&1)*32 cols).
template<int NIT>
__device__ __forceinline__ void gemm_mainloop(
    uint32_t smA, uint32_t smB, uint32_t cpoff, uint32_t aoff, uint32_t boff,
    const __nv_bfloat16* Arow_g, const __nv_bfloat16* Brow_g, float acc[4][4][4])
{
    issue_stage(smA, smB, cpoff, Arow_g, Brow_g, 0);
    CP_COMMIT();
    issue_stage(smA, smB, cpoff, Arow_g + 64, Brow_g + 64, 1);
    CP_COMMIT();
    #pragma unroll
    for (int it = 0; it < NIT; it++) {
        CP_WAIT1();
        __syncthreads();
        int s = it % 3;
        gemm_chunk64(smA + s * STG + aoff, smB + s * STG + boff, acc);
        if (it + 2 < NIT)
            issue_stage(smA, smB, cpoff, Arow_g + (it + 2) * 64, Brow_g + (it + 2) * 64,
                        (it + 2) % 3);
        CP_COMMIT();
    }
}

// ===========================================================================
// K-1 xbf: x f32 -> bf16
// ===========================================================================
__global__ __launch_bounds__(256) void xbf_kernel(const float* __restrict__ x)
{
    size_t i = ((size_t)blockIdx.x * 256 + threadIdx.x) * 8;
    float4 a = *(const float4*)(x + i);
    float4 b = *(const float4*)(x + i + 4);
    uint4 o;
    o.x = packbf2(a.x, a.y); o.y = packbf2(a.z, a.w);
    o.z = packbf2(b.x, b.y); o.w = packbf2(b.z, b.w);
    *(uint4*)&g_Xbf[i] = o;
}

// ===========================================================================
// K0 prep: weights -> bf16 transposed
// ===========================================================================
__global__ __launch_bounds__(256) void prep_kernel(
    const float* __restrict__ wt, const float* __restrict__ wp,
    const float* __restrict__ wg, const float* __restrict__ wo)
{
    int idx = blockIdx.x * 256 + threadIdx.x;
    if (idx < NPROJ * C_IN) {
        int k = idx & 511, n = idx >> 9;
        float v = (n < 64)  ? wt[k * CK + n]
                : (n < 128) ? wp[k * CK + (n - 64)]
                            : wg[k * CV + (n - 128)];
        g_WcatT[idx] = __float2bfloat16(v);
    } else if (idx < NPROJ * C_IN + C_IN * CV) {
        int i2 = idx - NPROJ * C_IN;
        int k = i2 & 255, n = i2 >> 8;
        g_WoT[i2] = __float2bfloat16(wo[(size_t)k * C_IN + n]);
    }
}

// ===========================================================================
// K1 proj: Y[32768,384] = g_Xbf @ WcatT^T.  grid (3, 256)
// ===========================================================================
__global__ __launch_bounds__(256, 2) void proj_kernel()
{
    extern __shared__ unsigned char sm[];
    const int m0 = blockIdx.y * 128, n0 = blockIdx.x * 128;
    const int tid = threadIdx.x, warp = tid >> 5, lane = tid & 31;
    const int wm = warp >> 2, wn = warp & 3, g = lane >> 2, t = lane & 3;

    uint32_t smA = smem_u32(sm), smB = smA + 3 * STG;
    uint32_t cpoff = (uint32_t)((tid >> 1) * 144 + (tid & 1) * 64);
    uint32_t aoff = a_lane_off(wm, lane), boff = b_lane_off(wn, lane);

    float acc[4][4][4];
    #pragma unroll
    for (int mi = 0; mi < 4; mi++)
        #pragma unroll
        for (int ni = 0; ni < 4; ni++)
            #pragma unroll
            for (int j = 0; j < 4; j++) acc[mi][ni][j] = 0.f;

    const __nv_bfloat16* Arow = g_Xbf   + (size_t)(m0 + (tid >> 1)) * C_IN + (tid & 1) * 32;
    const __nv_bfloat16* Brow = g_WcatT + (size_t)(n0 + (tid >> 1)) * C_IN + (tid & 1) * 32;
    gemm_mainloop<C_IN / 64>(smA, smB, cpoff, aoff, boff, Arow, Brow, acc);

    #pragma unroll
    for (int mi = 0; mi < 4; mi++)
        #pragma unroll
        for (int ni = 0; ni < 4; ni++) {
            int row = m0 + wm * 64 + mi * 16 + g;
            int col = n0 + wn * 32 + ni * 8 + 2 * t;
            *(unsigned*)&g_Y[(size_t)row * NPROJ + col] =
                packbf2(acc[mi][ni][0], acc[mi][ni][1]);
            *(unsigned*)&g_Y[(size_t)(row + 8) * NPROJ + col] =
                packbf2(acc[mi][ni][2], acc[mi][ni][3]);
        }
}

// ===========================================================================
// K2a poolphi: phi -> g_phiP [b][p][ck]
// ===========================================================================
__global__ __launch_bounds__(256) void poolphi_kernel()
{
    int idx = blockIdx.x * 256 + threadIdx.x;     // 524288 total
    int j = idx & 63, pp = (idx >> 6) & 1023, b = idx >> 16;
    int h2 = pp >> 5, w2 = pp & 31;
    size_t base = (size_t)b * HW;
    float m = -1e30f;
    #pragma unroll
    for (int dh = 0; dh < 2; dh++)
        #pragma unroll
        for (int dw = 0; dw < 2; dw++) {
            int p = (2 * h2 + dh) * 64 + 2 * w2 + dw;
            m = fmaxf(m, __bfloat162float(g_Y[(base + p) * NPROJ + 64 + j]));
        }
    g_phiP[idx] = __float2bfloat16(m);
}

// ===========================================================================
// K2b poolvT: g (Y cols 128..383) -> pooled + transposed g_vT [b][v][p]
// CTA: (pp-tile 64, v-tile 32, b).  smem-staged transpose, uint4 I/O.
// ===========================================================================
__global__ __launch_bounds__(256) void poolvT_kernel()
{
    __shared__ __nv_bfloat16 smT[32][72];
    const int b = blockIdx.z, v0 = blockIdx.y * 32, pp0 = blockIdx.x * 64;
    const int tid = threadIdx.x;

    // phase 1: pool 8 consecutive v per thread
    {
        int pp_l = tid & 63, vg = tid >> 6;   // vg 0..3
        int pp = pp0 + pp_l, h2 = pp >> 5, w2 = pp & 31;
        const __nv_bfloat16* base =
            g_Y + (size_t)b * HW * NPROJ + 128 + v0 + vg * 8;
        int p00 = (2 * h2) * 64 + 2 * w2;
        uint4 u0 = *(const uint4*)(base + (size_t)p00 * NPROJ);
        uint4 u1 = *(const uint4*)(base + (size_t)(p00 + 1) * NPROJ);
        uint4 u2 = *(const uint4*)(base + (size_t)(p00 + 64) * NPROJ);
        uint4 u3 = *(const uint4*)(base + (size_t)(p00 + 65) * NPROJ);
        const __nv_bfloat162* a0 = (const __nv_bfloat162*)&u0;
        const __nv_bfloat162* a1 = (const __nv_bfloat162*)&u1;
        const __nv_bfloat162* a2 = (const __nv_bfloat162*)&u2;
        const __nv_bfloat162* a3 = (const __nv_bfloat162*)&u3;
        #pragma unroll
        for (int q = 0; q < 4; q++) {
            __nv_bfloat162 m = __hmax2(__hmax2(a0[q], a1[q]), __hmax2(a2[q], a3[q]));
            smT[vg * 8 + 2 * q][pp_l]     = __low2bfloat16(m);
            smT[vg * 8 + 2 * q + 1][pp_l] = __high2bfloat16(m);
        }
    }
    __syncthreads();
    // phase 2: write transposed, 8 pp per thread (uint4)
    {
        int v_l = tid & 31, ppc = tid >> 5;
        uint4 val = *(const uint4*)&smT[v_l][ppc * 8];
        *(uint4*)&g_vT[((size_t)b * CV + v0 + v_l) * HWP + pp0 + ppc * 8] = val;
    }
}

// ===========================================================================
// K3: S = Q @ phi^T -> softmax -> P, S register-resident.
// M-tile 16, 8 warps, cp.async 3-stage K staging.
// Smem: Qs[16][72] @0 (2304) | red f32[16*8] @2304 (512) | Ks 3x18432 @2816
// ===========================================================================
#define S_SMEM (2816 + 3 * STG)   // 58112

__global__ __launch_bounds__(256, 2) void s_softmax_kernel()
{
    extern __shared__ unsigned char sm[];
    __nv_bfloat16* Qs = (__nv_bfloat16*)(sm);
    float*        red = (float*)(sm + 2304);
    const uint32_t KsB = smem_u32(sm) + 2816;

    const int tid = threadIdx.x, warp = tid >> 5, lane = tid & 31;
    const int g = lane >> 2, t = lane & 3;
    const int m0 = blockIdx.x * 16, b = blockIdx.y;

    // Q tile [16][64]
    if (tid < 128) {
        int r = tid >> 3, c0 = (tid & 7) * 8;
        const uint2* src = (const uint2*)&g_Y[(size_t)(b * HW + m0 + r) * NPROJ + c0];
        uint2* dst = (uint2*)&Qs[r * 72 + c0];
        dst[0] = src[0]; dst[1] = src[1];
    }

    // K staging (cp.async)
    const uint32_t kcp = KsB + (uint32_t)((tid >> 1) * 144 + (tid & 1) * 64);
    const __nv_bfloat16* Ksrc =
        g_phiP + ((size_t)b * HWP + (tid >> 1)) * CK + (tid & 1) * 32;
    #pragma unroll
    for (int j = 0; j < 4; j++) cp16(kcp + j * 16, Ksrc + j * 8);
    CP_COMMIT();
    #pragma unroll
    for (int j = 0; j < 4; j++) cp16(kcp + STG + j * 16, Ksrc + 128 * CK + j * 8);
    CP_COMMIT();

    __syncthreads();   // Qs visible

    // Q fragments (4 k16 steps)
    unsigned qa[4][4];
    #pragma unroll
    for (int kk = 0; kk < 4; kk++) {
        const __nv_bfloat16* p0 = Qs + g * 72 + kk * 16 + 2 * t;
        qa[kk][0] = *(const unsigned*)p0;
        qa[kk][1] = *(const unsigned*)(p0 + 8 * 72);
        qa[kk][2] = *(const unsigned*)(p0 + 8);
        qa[kk][3] = *(const unsigned*)(p0 + 8 * 72 + 8);
    }

    const uint32_t kslane = (uint32_t)((warp * 16 + (lane & 7)) * 144 + (lane >> 3) * 16);

    float sacc[2][8][4];
    #pragma unroll
    for (int ni = 0; ni < 2; ni++)
        #pragma unroll
        for (int ch = 0; ch < 8; ch++)
            #pragma unroll
            for (int j = 0; j < 4; j++) sacc[ni][ch][j] = 0.f;

    #pragma unroll
    for (int ch = 0; ch < 8; ch++) {
        CP_WAIT1();
        __syncthreads();
        uint32_t kbase = KsB + (uint32_t)(ch % 3) * STG + kslane;
        #pragma unroll
        for (int ni = 0; ni < 2; ni++) {
            unsigned b01[4], b23[4];
            ldsm4(b01, kbase + (uint32_t)ni * 8 * 144);
            ldsm4(b23, kbase + (uint32_t)ni * 8 * 144 + 64);
            mma16816(sacc[ni][ch], qa[0], &b01[0]);
            mma16816(sacc[ni][ch], qa[1], &b01[2]);
            mma16816(sacc[ni][ch], qa[2], &b23[0]);
            mma16816(sacc[ni][ch], qa[3], &b23[2]);
        }
        if (ch + 2 < 8) {
            const __nv_bfloat16* src = Ksrc + (size_t)(ch + 2) * 128 * CK;
            uint32_t dst = KsB + (uint32_t)((ch + 2) % 3) * STG +
                           (uint32_t)((tid >> 1) * 144 + (tid & 1) * 64);
            #pragma unroll
            for (int j = 0; j < 4; j++) cp16(dst + j * 16, src + j * 8);
        }
        CP_COMMIT();
    }

    // -------- register softmax: thread rows g (vals [0..1]) and g+8 ([2..3]) --------
    float mx0 = -1e30f, mx1 = -1e30f;
    #pragma unroll
    for (int ni = 0; ni < 2; ni++)
        #pragma unroll
        for (int ch = 0; ch < 8; ch++) {
            mx0 = fmaxf(mx0, fmaxf(sacc[ni][ch][0], sacc[ni][ch][1]));
            mx1 = fmaxf(mx1, fmaxf(sacc[ni][ch][2], sacc[ni][ch][3]));
        }
    mx0 = fmaxf(mx0, __shfl_xor_sync(0xffffffffu, mx0, 1));
    mx0 = fmaxf(mx0, __shfl_xor_sync(0xffffffffu, mx0, 2));
    mx1 = fmaxf(mx1, __shfl_xor_sync(0xffffffffu, mx1, 1));
    mx1 = fmaxf(mx1, __shfl_xor_sync(0xffffffffu, mx1, 2));
    if (t == 0) { red[g * 8 + warp] = mx0; red[(g + 8) * 8 + warp] = mx1; }
    __syncthreads();
    float M0 = -1e30f, M1 = -1e30f;
    #pragma unroll
    for (int w = 0; w < 8; w++) {
        M0 = fmaxf(M0, red[g * 8 + w]);
        M1 = fmaxf(M1, red[(g + 8) * 8 + w]);
    }
    __syncthreads();   // before red reuse for sums

    float s0 = 0.f, s1 = 0.f;
    #pragma unroll
    for (int ni = 0; ni < 2; ni++)
        #pragma unroll
        for (int ch = 0; ch < 8; ch++) {
            float e0 = __expf(sacc[ni][ch][0] - M0);
            float e1 = __expf(sacc[ni][ch][1] - M0);
            float e2 = __expf(sacc[ni][ch][2] - M1);
            float e3 = __expf(sacc[ni][ch][3] - M1);
            sacc[ni][ch][0] = e0; sacc[ni][ch][1] = e1;
            sacc[ni][ch][2] = e2; sacc[ni][ch][3] = e3;
            s0 += e0 + e1; s1 += e2 + e3;
        }
    s0 += __shfl_xor_sync(0xffffffffu, s0, 1);
    s0 += __shfl_xor_sync(0xffffffffu, s0, 2);
    s1 += __shfl_xor_sync(0xffffffffu, s1, 1);
    s1 += __shfl_xor_sync(0xffffffffu, s1, 2);
    if (t == 0) { red[g * 8 + warp] = s0; red[(g + 8) * 8 + warp] = s1; }
    __syncthreads();
    float S0 = 0.f, S1 = 0.f;
    #pragma unroll
    for (int w = 0; w < 8; w++) {
        S0 += red[g * 8 + w];
        S1 += red[(g + 8) * 8 + w];
    }
    float inv0 = 1.f / S0, inv1 = 1.f / S1;

    __nv_bfloat16* P0 = g_P + (size_t)(b * HW + m0 + g) * HWP;
    __nv_bfloat16* P1 = g_P + (size_t)(b * HW + m0 + g + 8) * HWP;
    #pragma unroll
    for (int ch = 0; ch < 8; ch++)
        #pragma unroll
        for (int ni = 0; ni < 2; ni++) {
            int col = ch * 128 + warp * 16 + ni * 8 + 2 * t;
            *(unsigned*)(P0 + col) = packbf2(sacc[ni][ch][0] * inv0, sacc[ni][ch][1] * inv0);
            *(unsigned*)(P1 + col) = packbf2(sacc[ni][ch][2] * inv1, sacc[ni][ch][3] * inv1);
        }
}

// ===========================================================================
// K4 PV: O[b][4096,256] = P[b] @ V[b]^T.  grid (2, 32, 8)
// ===========================================================================
__global__ __launch_bounds__(256, 2) void pv_kernel()
{
    extern __shared__ unsigned char sm[];
    const int b = blockIdx.z, m0 = blockIdx.y * 128, n0 = blockIdx.x * 128;
    const int tid = threadIdx.x, warp = tid >> 5, lane = tid & 31;
    const int wm = warp >> 2, wn = warp & 3, g = lane >> 2, t = lane & 3;

    uint32_t smA = smem_u32(sm), smB = smA + 3 * STG;
    uint32_t cpoff = (uint32_t)((tid >> 1) * 144 + (tid & 1) * 64);
    uint32_t aoff = a_lane_off(wm, lane), boff = b_lane_off(wn, lane);

    float acc[4][4][4];
    #pragma unroll
    for (int mi = 0; mi < 4; mi++)
        #pragma unroll
        for (int ni = 0; ni < 4; ni++)
            #pragma unroll
            for (int j = 0; j < 4; j++) acc[mi][ni][j] = 0.f;

    const __nv_bfloat16* Arow =
        g_P  + (size_t)b * HW * HWP + (size_t)(m0 + (tid >> 1)) * HWP + (tid & 1) * 32;
    const __nv_bfloat16* Brow =
        g_vT + (size_t)b * CV * HWP + (size_t)(n0 + (tid >> 1)) * HWP + (tid & 1) * 32;
    gemm_mainloop<HWP / 64>(smA, smB, cpoff, aoff, boff, Arow, Brow, acc);

    #pragma unroll
    for (int mi = 0; mi < 4; mi++)
        #pragma unroll
        for (int ni = 0; ni < 4; ni++) {
            int row = b * HW + m0 + wm * 64 + mi * 16 + g;
            int col = n0 + wn * 32 + ni * 8 + 2 * t;
            *(unsigned*)&g_O[(size_t)row * CV + col] =
                packbf2(acc[mi][ni][0], acc[mi][ni][1]);
            *(unsigned*)&g_O[(size_t)(row + 8) * CV + col] =
                packbf2(acc[mi][ni][2], acc[mi][ni][3]);
        }
}

// ===========================================================================
// K5 out: out = x + gamma * (g_O @ w_o).  grid (4, 256)
// ===========================================================================
__global__ __launch_bounds__(256, 2) void out_kernel(
    const float* __restrict__ x, const float* __restrict__ gamma,
    float* __restrict__ out)
{
    extern __shared__ unsigned char sm[];
    const int m0 = blockIdx.y * 128, n0 = blockIdx.x * 128;
    const int tid = threadIdx.x, warp = tid >> 5, lane = tid & 31;
    const int wm = warp >> 2, wn = warp & 3, g = lane >> 2, t = lane & 3;

    uint32_t smA = smem_u32(sm), smB = smA + 3 * STG;
    uint32_t cpoff = (uint32_t)((tid >> 1) * 144 + (tid & 1) * 64);
    uint32_t aoff = a_lane_off(wm, lane), boff = b_lane_off(wn, lane);

    float acc[4][4][4];
    #pragma unroll
    for (int mi = 0; mi < 4; mi++)
        #pragma unroll
        for (int ni = 0; ni < 4; ni++)
            #pragma unroll
            for (int j = 0; j < 4; j++) acc[mi][ni][j] = 0.f;

    const __nv_bfloat16* Arow = g_O   + (size_t)(m0 + (tid >> 1)) * CV + (tid & 1) * 32;
    const __nv_bfloat16* Brow = g_WoT + (size_t)(n0 + (tid >> 1)) * CV + (tid & 1) * 32;
    gemm_mainloop<CV / 64>(smA, smB, cpoff, aoff, boff, Arow, Brow, acc);

    const float gam = gamma[0];
    #pragma unroll
    for (int mi = 0; mi < 4; mi++)
        #pragma unroll
        for (int ni = 0; ni < 4; ni++) {
            int row = m0 + wm * 64 + mi * 16 + g;
            int col = n0 + wn * 32 + ni * 8 + 2 * t;
            {
                float2 xv = *(const float2*)&x[(size_t)row * C_IN + col];
                float2 ov = make_float2(xv.x + gam * acc[mi][ni][0],
                                        xv.y + gam * acc[mi][ni][1]);
                *(float2*)&out[(size_t)row * C_IN + col] = ov;
            }
            {
                float2 xv = *(const float2*)&x[(size_t)(row + 8) * C_IN + col];
                float2 ov = make_float2(xv.x + gam * acc[mi][ni][2],
                                        xv.y + gam * acc[mi][ni][3]);
                *(float2*)&out[(size_t)(row + 8) * C_IN + col] = ov;
            }
        }
}

// ===========================================================================
extern "C" void kernel_launch(void* const* d_in, const int* in_sizes, int n_in,
                              void* d_out, int out_size)
{
    const float* x       = (const float*)d_in[0];
    const float* w_theta = (const float*)d_in[1];
    const float* w_phi   = (const float*)d_in[2];
    const float* w_g     = (const float*)d_in[3];
    const float* w_o     = (const float*)d_in[4];
    const float* gamma   = (const float*)d_in[5];
    float* out = (float*)d_out;
    (void)in_sizes; (void)n_in; (void)out_size;

    cudaFuncSetAttribute(proj_kernel, cudaFuncAttributeMaxDynamicSharedMemorySize, GSMEM);
    cudaFuncSetAttribute(pv_kernel,   cudaFuncAttributeMaxDynamicSharedMemorySize, GSMEM);
    cudaFuncSetAttribute(out_kernel,  cudaFuncAttributeMaxDynamicSharedMemorySize, GSMEM);
    cudaFuncSetAttribute(s_softmax_kernel, cudaFuncAttributeMaxDynamicSharedMemorySize, S_SMEM);

    // K0: weight transpose/convert + x -> bf16
    {
        int total = NPROJ * C_IN + C_IN * CV;
        prep_kernel<<<(total + 255) / 256, 256>>>(w_theta, w_phi, w_g, w_o);
    }
    xbf_kernel<<<(M_TOT * C_IN / 8) / 256, 256>>>(x);
    // K1: projections
    proj_kernel<<<dim3(NPROJ / 128, M_TOT / 128), 256, GSMEM>>>();
    // K2: pooling
    poolphi_kernel<<<(8 * HWP * CK) / 256, 256>>>();
    poolvT_kernel<<<dim3(HWP / 64, CV / 32, 8), 256>>>();
    // K3: S + softmax -> P
    s_softmax_kernel<<<dim3(HW / 16, 8), 256, S_SMEM>>>();
    // K4: P @ V
    pv_kernel<<<dim3(CV / 128, HW / 128, 8), 256, GSMEM>>>();
    // K5: output projection + residual
    out_kernel<<<dim3(C_IN / 128, M_TOT / 128), 256, GSMEM>>>(x, gamma, out);
}

// round 11
// speedup vs baseline: 2.9067x; 1.0802x over previous
#include <cuda_runtime.h>
#include <cuda_bf16.h>
#include <cstdint>

// x: [8,64,64,512] f32; w_theta [512,64]; w_phi [512,64]; w_g [512,256]; w_o [256,512]; gamma [1]
#define M_TOT   32768
#define C_IN    512
#define CK      64
#define CV      256
#define NPROJ   384
#define HW      4096
#define HWP     1024

// -------------------- scratch (device globals) --------------------
__device__ __nv_bfloat16 g_WcatT[(size_t)NPROJ * C_IN];   // [384][512]  W^T (theta|phi|g)
__device__ __nv_bfloat16 g_WoT[(size_t)C_IN * CV];        // [512][256]  w_o^T
__device__ __nv_bfloat16 g_Xbf[(size_t)M_TOT * C_IN];     // x in bf16
__device__ __nv_bfloat16 g_Y[(size_t)M_TOT * NPROJ];      // proj outputs
__device__ __nv_bfloat16 g_phiP[(size_t)8 * HWP * CK];    // pooled phi [b][p][ck]
__device__ __nv_bfloat16 g_vT[(size_t)8 * CV * HWP];      // pooled g, transposed [b][v][p]
__device__ __nv_bfloat16 g_P[(size_t)8 * HW * HWP];       // softmax probs
__device__ __nv_bfloat16 g_O[(size_t)M_TOT * CV];         // attn output

// ---------------------------------------------------------------------------
__device__ __forceinline__ uint32_t smem_u32(const void* p) {
    uint32_t a;
    asm("{ .reg .u64 t; cvta.to.shared.u64 t, %1; cvt.u32.u64 %0, t; }" : "=r"(a) : "l"(p));
    return a;
}
__device__ __forceinline__ void mma16816(float* d, const unsigned* a, const unsigned* b) {
    asm volatile(
        "mma.sync.aligned.m16n8k16.row.col.f32.bf16.bf16.f32 "
        "{%0,%1,%2,%3}, {%4,%5,%6,%7}, {%8,%9}, {%0,%1,%2,%3};\n"
        : "+f"(d[0]), "+f"(d[1]), "+f"(d[2]), "+f"(d[3])
        : "r"(a[0]), "r"(a[1]), "r"(a[2]), "r"(a[3]), "r"(b[0]), "r"(b[1]));
}
__device__ __forceinline__ void ldsm4(unsigned r[4], uint32_t addr) {
    asm volatile("ldmatrix.sync.aligned.m8n8.x4.shared.b16 {%0,%1,%2,%3}, [%4];"
                 : "=r"(r[0]), "=r"(r[1]), "=r"(r[2]), "=r"(r[3]) : "r"(addr));
}
__device__ __forceinline__ void cp16(uint32_t d, const void* g) {
    asm volatile("cp.async.cg.shared.global [%0], [%1], 16;" :: "r"(d), "l"(g));
}
#define CP_COMMIT() asm volatile("cp.async.commit_group;" ::: "memory")
#define CP_WAIT1()  asm volatile("cp.async.wait_group 1;"  ::: "memory")

__device__ __forceinline__ unsigned packbf2(float x, float y) {
    __nv_bfloat162 h = __floats2bfloat162_rn(x, y);
    return *(unsigned*)&h;
}

// Coalesced 16-col bf16 store: lane (g,t) holds u0 = cols colbase+2t..+1 and
// u1 = cols colbase+8+2t..+1 of one row. Quad-exchange via shfl so lane t
// writes 8 contiguous bytes at colbase+4t (32B contiguous per quad).
__device__ __forceinline__ void store16(__nv_bfloat16* rowptr, int colbase,
                                        unsigned u0, unsigned u1, int t, int lane)
{
    int srcl = (lane & ~3) | ((2 * t) & 3);
    unsigned a  = __shfl_sync(0xffffffffu, u0, srcl);
    unsigned b  = __shfl_sync(0xffffffffu, u1, srcl);
    unsigned a2 = __shfl_sync(0xffffffffu, u0, srcl + 1);
    unsigned b2 = __shfl_sync(0xffffffffu, u1, srcl + 1);
    uint2 w;
    w.x = (t < 2) ? a : b;
    w.y = (t < 2) ? a2 : b2;
    *(uint2*)(rowptr + colbase + 4 * t) = w;
}

// ---------------------------------------------------------------------------
// Shared per-warp compute: one K=64 chunk of a [*,128-or-256][72] tile pair.
// A tile 128 rows x 144B; B tile (128 or 256) rows x 144B.
// ---------------------------------------------------------------------------
#define ASTG 18432             // 128*144
#define BSTG 36864             // 256*144
#define GSMEM   (6 * ASTG)     // proj: 3-stage A + 3-stage B(128 rows)
#define WSMEM   (3 * ASTG + 3 * BSTG)   // wide: 165888

__device__ __forceinline__ uint32_t a_lane_off(int wm, int lane) {
    return (uint32_t)((wm * 64 + (lane & 15)) * 144 + ((lane >> 4) << 4));
}
__device__ __forceinline__ uint32_t b_lane_off(int wn, int lane) {
    return (uint32_t)((wn * 32 + (lane & 7) + ((lane & 16) ? 8 : 0)) * 144
                      + ((lane & 8) ? 16 : 0));
}
__device__ __forceinline__ void gemm_chunk64(uint32_t aBase, uint32_t bBase, float acc[4][4][4])
{
    #pragma unroll
    for (int k16 = 0; k16 < 4; k16++) {
        unsigned a[4][4], bb[2][4];
        #pragma unroll
        for (int mi = 0; mi < 4; mi++) ldsm4(a[mi], aBase + mi * 16 * 144 + k16 * 32);
        #pragma unroll
        for (int np = 0; np < 2; np++) ldsm4(bb[np], bBase + np * 16 * 144 + k16 * 32);
        #pragma unroll
        for (int mi = 0; mi < 4; mi++) {
            mma16816(acc[mi][0], a[mi], &bb[0][0]);
            mma16816(acc[mi][1], a[mi], &bb[0][2]);
            mma16816(acc[mi][2], a[mi], &bb[1][0]);
            mma16816(acc[mi][3], a[mi], &bb[1][2]);
        }
    }
}

// Narrow (128x128, 256 thr) mainloop — as round 9.
__device__ __forceinline__ void issue_stage(uint32_t smA, uint32_t smB, uint32_t cpoff,
    const __nv_bfloat16* ga, const __nv_bfloat16* gb, int s)
{
    uint32_t da = smA + s * ASTG + cpoff;
    uint32_t db = smB + s * ASTG + cpoff;
    #pragma unroll
    for (int j = 0; j < 4; j++) {
        cp16(da + j * 16, ga + j * 8);
        cp16(db + j * 16, gb + j * 8);
    }
}
template<int NIT>
__device__ __forceinline__ void gemm_mainloop(
    uint32_t smA, uint32_t smB, uint32_t cpoff, uint32_t aoff, uint32_t boff,
    const __nv_bfloat16* Arow_g, const __nv_bfloat16* Brow_g, float acc[4][4][4])
{
    issue_stage(smA, smB, cpoff, Arow_g, Brow_g, 0);
    CP_COMMIT();
    issue_stage(smA, smB, cpoff, Arow_g + 64, Brow_g + 64, 1);
    CP_COMMIT();
    #pragma unroll
    for (int it = 0; it < NIT; it++) {
        CP_WAIT1();
        __syncthreads();
        int s = it % 3;
        gemm_chunk64(smA + s * ASTG + aoff, smB + s * ASTG + boff, acc);
        if (it + 2 < NIT)
            issue_stage(smA, smB, cpoff, Arow_g + (it + 2) * 64, Brow_g + (it + 2) * 64,
                        (it + 2) % 3);
        CP_COMMIT();
    }
}

// Wide (128x256, 512 thr) mainloop. cpA covers A (thread: row tid>>2, 16 els),
// cpB covers B (thread: row tid>>1 of 256, 32 els).
template<int NIT>
__device__ __forceinline__ void wide_mainloop(
    uint32_t smA, uint32_t smB, uint32_t cpA, uint32_t cpB,
    uint32_t aoff, uint32_t boff,
    const __nv_bfloat16* Ag, const __nv_bfloat16* Bg, float acc[4][4][4])
{
    #pragma unroll
    for (int s = 0; s < 2; s++) {
        uint32_t da = smA + s * ASTG + cpA;
        cp16(da, Ag + s * 64); cp16(da + 16, Ag + s * 64 + 8);
        uint32_t db = smB + s * BSTG + cpB;
        #pragma unroll
        for (int j = 0; j < 4; j++) cp16(db + j * 16, Bg + s * 64 + j * 8);
        CP_COMMIT();
    }
    #pragma unroll
    for (int it = 0; it < NIT; it++) {
        CP_WAIT1();
        __syncthreads();
        int s = it % 3;
        gemm_chunk64(smA + s * ASTG + aoff, smB + s * BSTG + boff, acc);
        if (it + 2 < NIT) {
            int s2 = (it + 2) % 3;
            uint32_t da = smA + s2 * ASTG + cpA;
            cp16(da, Ag + (it + 2) * 64); cp16(da + 16, Ag + (it + 2) * 64 + 8);
            uint32_t db = smB + s2 * BSTG + cpB;
            #pragma unroll
            for (int j = 0; j < 4; j++) cp16(db + j * 16, Bg + (it + 2) * 64 + j * 8);
        }
        CP_COMMIT();
    }
}

// ===========================================================================
// K-1 xbf: x f32 -> bf16
// ===========================================================================
__global__ __launch_bounds__(256) void xbf_kernel(const float* __restrict__ x)
{
    size_t i = ((size_t)blockIdx.x * 256 + threadIdx.x) * 8;
    float4 a = *(const float4*)(x + i);
    float4 b = *(const float4*)(x + i + 4);
    uint4 o;
    o.x = packbf2(a.x, a.y); o.y = packbf2(a.z, a.w);
    o.z = packbf2(b.x, b.y); o.w = packbf2(b.z, b.w);
    *(uint4*)&g_Xbf[i] = o;
}

// ===========================================================================
// K0 prep: weights -> bf16 transposed
// ===========================================================================
__global__ __launch_bounds__(256) void prep_kernel(
    const float* __restrict__ wt, const float* __restrict__ wp,
    const float* __restrict__ wg, const float* __restrict__ wo)
{
    int idx = blockIdx.x * 256 + threadIdx.x;
    if (idx < NPROJ * C_IN) {
        int k = idx & 511, n = idx >> 9;
        float v = (n < 64)  ? wt[k * CK + n]
                : (n < 128) ? wp[k * CK + (n - 64)]
                            : wg[k * CV + (n - 128)];
        g_WcatT[idx] = __float2bfloat16(v);
    } else if (idx < NPROJ * C_IN + C_IN * CV) {
        int i2 = idx - NPROJ * C_IN;
        int k = i2 & 255, n = i2 >> 8;
        g_WoT[i2] = __float2bfloat16(wo[(size_t)k * C_IN + n]);
    }
}

// ===========================================================================
// K1 proj: Y[32768,384] = g_Xbf @ WcatT^T.  grid (3, 256), 256 thr
// ===========================================================================
__global__ __launch_bounds__(256, 2) void proj_kernel()
{
    extern __shared__ unsigned char sm[];
    const int m0 = blockIdx.y * 128, n0 = blockIdx.x * 128;
    const int tid = threadIdx.x, warp = tid >> 5, lane = tid & 31;
    const int wm = warp >> 2, wn = warp & 3, g = lane >> 2, t = lane & 3;

    uint32_t smA = smem_u32(sm), smB = smA + 3 * ASTG;
    uint32_t cpoff = (uint32_t)((tid >> 1) * 144 + (tid & 1) * 64);
    uint32_t aoff = a_lane_off(wm, lane), boff = b_lane_off(wn, lane);

    float acc[4][4][4];
    #pragma unroll
    for (int mi = 0; mi < 4; mi++)
        #pragma unroll
        for (int ni = 0; ni < 4; ni++)
            #pragma unroll
            for (int j = 0; j < 4; j++) acc[mi][ni][j] = 0.f;

    const __nv_bfloat16* Arow = g_Xbf   + (size_t)(m0 + (tid >> 1)) * C_IN + (tid & 1) * 32;
    const __nv_bfloat16* Brow = g_WcatT + (size_t)(n0 + (tid >> 1)) * C_IN + (tid & 1) * 32;
    gemm_mainloop<C_IN / 64>(smA, smB, cpoff, aoff, boff, Arow, Brow, acc);

    #pragma unroll
    for (int mi = 0; mi < 4; mi++)
        #pragma unroll
        for (int nip = 0; nip < 2; nip++) {
            int row = m0 + wm * 64 + mi * 16 + g;
            int colbase = n0 + wn * 32 + nip * 16;
            unsigned u0 = packbf2(acc[mi][2*nip][0],   acc[mi][2*nip][1]);
            unsigned u1 = packbf2(acc[mi][2*nip+1][0], acc[mi][2*nip+1][1]);
            store16(g_Y + (size_t)row * NPROJ, colbase, u0, u1, t, lane);
            unsigned v0 = packbf2(acc[mi][2*nip][2],   acc[mi][2*nip][3]);
            unsigned v1 = packbf2(acc[mi][2*nip+1][2], acc[mi][2*nip+1][3]);
            store16(g_Y + (size_t)(row + 8) * NPROJ, colbase, v0, v1, t, lane);
        }
}

// ===========================================================================
// K2a poolphi: phi -> g_phiP [b][p][ck]
// ===========================================================================
__global__ __launch_bounds__(256) void poolphi_kernel()
{
    int idx = blockIdx.x * 256 + threadIdx.x;
    int j = idx & 63, pp = (idx >> 6) & 1023, b = idx >> 16;
    int h2 = pp >> 5, w2 = pp & 31;
    size_t base = (size_t)b * HW;
    float m = -1e30f;
    #pragma unroll
    for (int dh = 0; dh < 2; dh++)
        #pragma unroll
        for (int dw = 0; dw < 2; dw++) {
            int p = (2 * h2 + dh) * 64 + 2 * w2 + dw;
            m = fmaxf(m, __bfloat162float(g_Y[(base + p) * NPROJ + 64 + j]));
        }
    g_phiP[idx] = __float2bfloat16(m);
}

// ===========================================================================
// K2b poolvT: g (Y cols 128..383) -> pooled + transposed g_vT [b][v][p]
// ===========================================================================
__global__ __launch_bounds__(256) void poolvT_kernel()
{
    __shared__ __nv_bfloat16 smT[32][72];
    const int b = blockIdx.z, v0 = blockIdx.y * 32, pp0 = blockIdx.x * 64;
    const int tid = threadIdx.x;
    {
        int pp_l = tid & 63, vg = tid >> 6;
        int pp = pp0 + pp_l, h2 = pp >> 5, w2 = pp & 31;
        const __nv_bfloat16* base =
            g_Y + (size_t)b * HW * NPROJ + 128 + v0 + vg * 8;
        int p00 = (2 * h2) * 64 + 2 * w2;
        uint4 u0 = *(const uint4*)(base + (size_t)p00 * NPROJ);
        uint4 u1 = *(const uint4*)(base + (size_t)(p00 + 1) * NPROJ);
        uint4 u2 = *(const uint4*)(base + (size_t)(p00 + 64) * NPROJ);
        uint4 u3 = *(const uint4*)(base + (size_t)(p00 + 65) * NPROJ);
        const __nv_bfloat162* a0 = (const __nv_bfloat162*)&u0;
        const __nv_bfloat162* a1 = (const __nv_bfloat162*)&u1;
        const __nv_bfloat162* a2 = (const __nv_bfloat162*)&u2;
        const __nv_bfloat162* a3 = (const __nv_bfloat162*)&u3;
        #pragma unroll
        for (int q = 0; q < 4; q++) {
            __nv_bfloat162 m = __hmax2(__hmax2(a0[q], a1[q]), __hmax2(a2[q], a3[q]));
            smT[vg * 8 + 2 * q][pp_l]     = __low2bfloat16(m);
            smT[vg * 8 + 2 * q + 1][pp_l] = __high2bfloat16(m);
        }
    }
    __syncthreads();
    {
        int v_l = tid & 31, ppc = tid >> 5;
        uint4 val = *(const uint4*)&smT[v_l][ppc * 8];
        *(uint4*)&g_vT[((size_t)b * CV + v0 + v_l) * HWP + pp0 + ppc * 8] = val;
    }
}

// ===========================================================================
// K3: S = Q @ phi^T -> softmax -> P (register-resident S), M-tile 16.
// ===========================================================================
#define S_SMEM (2816 + 3 * ASTG)   // 58112

__global__ __launch_bounds__(256, 2) void s_softmax_kernel()
{
    extern __shared__ unsigned char sm[];
    __nv_bfloat16* Qs = (__nv_bfloat16*)(sm);
    float*        red = (float*)(sm + 2304);
    const uint32_t KsB = smem_u32(sm) + 2816;

    const int tid = threadIdx.x, warp = tid >> 5, lane = tid & 31;
    const int g = lane >> 2, t = lane & 3;
    const int m0 = blockIdx.x * 16, b = blockIdx.y;

    if (tid < 128) {
        int r = tid >> 3, c0 = (tid & 7) * 8;
        const uint2* src = (const uint2*)&g_Y[(size_t)(b * HW + m0 + r) * NPROJ + c0];
        uint2* dst = (uint2*)&Qs[r * 72 + c0];
        dst[0] = src[0]; dst[1] = src[1];
    }

    const uint32_t kcp = KsB + (uint32_t)((tid >> 1) * 144 + (tid & 1) * 64);
    const __nv_bfloat16* Ksrc =
        g_phiP + ((size_t)b * HWP + (tid >> 1)) * CK + (tid & 1) * 32;
    #pragma unroll
    for (int j = 0; j < 4; j++) cp16(kcp + j * 16, Ksrc + j * 8);
    CP_COMMIT();
    #pragma unroll
    for (int j = 0; j < 4; j++) cp16(kcp + ASTG + j * 16, Ksrc + 128 * CK + j * 8);
    CP_COMMIT();

    __syncthreads();

    unsigned qa[4][4];
    #pragma unroll
    for (int kk = 0; kk < 4; kk++) {
        const __nv_bfloat16* p0 = Qs + g * 72 + kk * 16 + 2 * t;
        qa[kk][0] = *(const unsigned*)p0;
        qa[kk][1] = *(const unsigned*)(p0 + 8 * 72);
        qa[kk][2] = *(const unsigned*)(p0 + 8);
        qa[kk][3] = *(const unsigned*)(p0 + 8 * 72 + 8);
    }

    const uint32_t kslane = (uint32_t)((warp * 16 + (lane & 7)) * 144 + (lane >> 3) * 16);

    float sacc[2][8][4];
    #pragma unroll
    for (int ni = 0; ni < 2; ni++)
        #pragma unroll
        for (int ch = 0; ch < 8; ch++)
            #pragma unroll
            for (int j = 0; j < 4; j++) sacc[ni][ch][j] = 0.f;

    #pragma unroll
    for (int ch = 0; ch < 8; ch++) {
        CP_WAIT1();
        __syncthreads();
        uint32_t kbase = KsB + (uint32_t)(ch % 3) * ASTG + kslane;
        #pragma unroll
        for (int ni = 0; ni < 2; ni++) {
            unsigned b01[4], b23[4];
            ldsm4(b01, kbase + (uint32_t)ni * 8 * 144);
            ldsm4(b23, kbase + (uint32_t)ni * 8 * 144 + 64);
            mma16816(sacc[ni][ch], qa[0], &b01[0]);
            mma16816(sacc[ni][ch], qa[1], &b01[2]);
            mma16816(sacc[ni][ch], qa[2], &b23[0]);
            mma16816(sacc[ni][ch], qa[3], &b23[2]);
        }
        if (ch + 2 < 8) {
            const __nv_bfloat16* src = Ksrc + (size_t)(ch + 2) * 128 * CK;
            uint32_t dst = KsB + (uint32_t)((ch + 2) % 3) * ASTG +
                           (uint32_t)((tid >> 1) * 144 + (tid & 1) * 64);
            #pragma unroll
            for (int j = 0; j < 4; j++) cp16(dst + j * 16, src + j * 8);
        }
        CP_COMMIT();
    }

    // register softmax
    float mx0 = -1e30f, mx1 = -1e30f;
    #pragma unroll
    for (int ni = 0; ni < 2; ni++)
        #pragma unroll
        for (int ch = 0; ch < 8; ch++) {
            mx0 = fmaxf(mx0, fmaxf(sacc[ni][ch][0], sacc[ni][ch][1]));
            mx1 = fmaxf(mx1, fmaxf(sacc[ni][ch][2], sacc[ni][ch][3]));
        }
    mx0 = fmaxf(mx0, __shfl_xor_sync(0xffffffffu, mx0, 1));
    mx0 = fmaxf(mx0, __shfl_xor_sync(0xffffffffu, mx0, 2));
    mx1 = fmaxf(mx1, __shfl_xor_sync(0xffffffffu, mx1, 1));
    mx1 = fmaxf(mx1, __shfl_xor_sync(0xffffffffu, mx1, 2));
    if (t == 0) { red[g * 8 + warp] = mx0; red[(g + 8) * 8 + warp] = mx1; }
    __syncthreads();
    float M0 = -1e30f, M1 = -1e30f;
    #pragma unroll
    for (int w = 0; w < 8; w++) {
        M0 = fmaxf(M0, red[g * 8 + w]);
        M1 = fmaxf(M1, red[(g + 8) * 8 + w]);
    }
    __syncthreads();

    float s0 = 0.f, s1 = 0.f;
    #pragma unroll
    for (int ni = 0; ni < 2; ni++)
        #pragma unroll
        for (int ch = 0; ch < 8; ch++) {
            float e0 = __expf(sacc[ni][ch][0] - M0);
            float e1 = __expf(sacc[ni][ch][1] - M0);
            float e2 = __expf(sacc[ni][ch][2] - M1);
            float e3 = __expf(sacc[ni][ch][3] - M1);
            sacc[ni][ch][0] = e0; sacc[ni][ch][1] = e1;
            sacc[ni][ch][2] = e2; sacc[ni][ch][3] = e3;
            s0 += e0 + e1; s1 += e2 + e3;
        }
    s0 += __shfl_xor_sync(0xffffffffu, s0, 1);
    s0 += __shfl_xor_sync(0xffffffffu, s0, 2);
    s1 += __shfl_xor_sync(0xffffffffu, s1, 1);
    s1 += __shfl_xor_sync(0xffffffffu, s1, 2);
    if (t == 0) { red[g * 8 + warp] = s0; red[(g + 8) * 8 + warp] = s1; }
    __syncthreads();
    float S0 = 0.f, S1 = 0.f;
    #pragma unroll
    for (int w = 0; w < 8; w++) {
        S0 += red[g * 8 + w];
        S1 += red[(g + 8) * 8 + w];
    }
    float inv0 = 1.f / S0, inv1 = 1.f / S1;

    __nv_bfloat16* P0 = g_P + (size_t)(b * HW + m0 + g) * HWP;
    __nv_bfloat16* P1 = g_P + (size_t)(b * HW + m0 + g + 8) * HWP;
    #pragma unroll
    for (int ch = 0; ch < 8; ch++) {
        int colbase = ch * 128 + warp * 16;
        unsigned u0 = packbf2(sacc[0][ch][0] * inv0, sacc[0][ch][1] * inv0);
        unsigned u1 = packbf2(sacc[1][ch][0] * inv0, sacc[1][ch][1] * inv0);
        store16(P0, colbase, u0, u1, t, lane);
        unsigned v0 = packbf2(sacc[0][ch][2] * inv1, sacc[0][ch][3] * inv1);
        unsigned v1 = packbf2(sacc[1][ch][2] * inv1, sacc[1][ch][3] * inv1);
        store16(P1, colbase, v0, v1, t, lane);
    }
}

// ===========================================================================
// K4 PV: O[b][4096,256] = P[b] @ V[b]^T.  128x256 tile, 512 thr, grid (32, 8)
// ===========================================================================
__global__ __launch_bounds__(512, 1) void pv_kernel()
{
    extern __shared__ unsigned char sm[];
    const int b = blockIdx.y, m0 = blockIdx.x * 128;
    const int tid = threadIdx.x, warp = tid >> 5, lane = tid & 31;
    const int wm = warp >> 3, wn = warp & 7, g = lane >> 2, t = lane & 3;

    uint32_t smA = smem_u32(sm), smB = smA + 3 * ASTG;
    uint32_t cpA = (uint32_t)((tid >> 2) * 144 + (tid & 3) * 32);
    uint32_t cpB = (uint32_t)((tid >> 1) * 144 + (tid & 1) * 64);
    uint32_t aoff = a_lane_off(wm, lane), boff = b_lane_off(wn, lane);

    float acc[4][4][4];
    #pragma unroll
    for (int mi = 0; mi < 4; mi++)
        #pragma unroll
        for (int ni = 0; ni < 4; ni++)
            #pragma unroll
            for (int j = 0; j < 4; j++) acc[mi][ni][j] = 0.f;

    const __nv_bfloat16* Ag =
        g_P  + (size_t)b * HW * HWP + (size_t)(m0 + (tid >> 2)) * HWP + (tid & 3) * 16;
    const __nv_bfloat16* Bg =
        g_vT + (size_t)b * CV * HWP + (size_t)(tid >> 1) * HWP + (tid & 1) * 32;
    wide_mainloop<HWP / 64>(smA, smB, cpA, cpB, aoff, boff, Ag, Bg, acc);

    #pragma unroll
    for (int mi = 0; mi < 4; mi++)
        #pragma unroll
        for (int nip = 0; nip < 2; nip++) {
            int row = b * HW + m0 + wm * 64 + mi * 16 + g;
            int colbase = wn * 32 + nip * 16;
            unsigned u0 = packbf2(acc[mi][2*nip][0],   acc[mi][2*nip][1]);
            unsigned u1 = packbf2(acc[mi][2*nip+1][0], acc[mi][2*nip+1][1]);
            store16(g_O + (size_t)row * CV, colbase, u0, u1, t, lane);
            unsigned v0 = packbf2(acc[mi][2*nip][2],   acc[mi][2*nip][3]);
            unsigned v1 = packbf2(acc[mi][2*nip+1][2], acc[mi][2*nip+1][3]);
            store16(g_O + (size_t)(row + 8) * CV, colbase, v0, v1, t, lane);
        }
}

// ===========================================================================
// K5 out: out = x + gamma * (g_O @ w_o).  128x256 tile, 512 thr, grid (2, 256)
// ===========================================================================
__global__ __launch_bounds__(512, 1) void out_kernel(
    const float* __restrict__ x, const float* __restrict__ gamma,
    float* __restrict__ out)
{
    extern __shared__ unsigned char sm[];
    const int n0 = blockIdx.x * 256, m0 = blockIdx.y * 128;
    const int tid = threadIdx.x, warp = tid >> 5, lane = tid & 31;
    const int wm = warp >> 3, wn = warp & 7, g = lane >> 2, t = lane & 3;

    uint32_t smA = smem_u32(sm), smB = smA + 3 * ASTG;
    uint32_t cpA = (uint32_t)((tid >> 2) * 144 + (tid & 3) * 32);
    uint32_t cpB = (uint32_t)((tid >> 1) * 144 + (tid & 1) * 64);
    uint32_t aoff = a_lane_off(wm, lane), boff = b_lane_off(wn, lane);

    float acc[4][4][4];
    #pragma unroll
    for (int mi = 0; mi < 4; mi++)
        #pragma unroll
        for (int ni = 0; ni < 4; ni++)
            #pragma unroll
            for (int j = 0; j < 4; j++) acc[mi][ni][j] = 0.f;

    const __nv_bfloat16* Ag = g_O   + (size_t)(m0 + (tid >> 2)) * CV + (tid & 3) * 16;
    const __nv_bfloat16* Bg = g_WoT + (size_t)(n0 + (tid >> 1)) * CV + (tid & 1) * 32;
    wide_mainloop<CV / 64>(smA, smB, cpA, cpB, aoff, boff, Ag, Bg, acc);

    const float gam = gamma[0];
    #pragma unroll
    for (int mi = 0; mi < 4; mi++)
        #pragma unroll
        for (int ni = 0; ni < 4; ni++) {
            int row = m0 + wm * 64 + mi * 16 + g;
            int col = n0 + wn * 32 + ni * 8 + 2 * t;
            {
                float2 xv = *(const float2*)&x[(size_t)row * C_IN + col];
                float2 ov = make_float2(xv.x + gam * acc[mi][ni][0],
                                        xv.y + gam * acc[mi][ni][1]);
                *(float2*)&out[(size_t)row * C_IN + col] = ov;
            }
            {
                float2 xv = *(const float2*)&x[(size_t)(row + 8) * C_IN + col];
                float2 ov = make_float2(xv.x + gam * acc[mi][ni][2],
                                        xv.y + gam * acc[mi][ni][3]);
                *(float2*)&out[(size_t)(row + 8) * C_IN + col] = ov;
            }
        }
}

// ===========================================================================
extern "C" void kernel_launch(void* const* d_in, const int* in_sizes, int n_in,
                              void* d_out, int out_size)
{
    const float* x       = (const float*)d_in[0];
    const float* w_theta = (const float*)d_in[1];
    const float* w_phi   = (const float*)d_in[2];
    const float* w_g     = (const float*)d_in[3];
    const float* w_o     = (const float*)d_in[4];
    const float* gamma   = (const float*)d_in[5];
    float* out = (float*)d_out;
    (void)in_sizes; (void)n_in; (void)out_size;

    cudaFuncSetAttribute(proj_kernel, cudaFuncAttributeMaxDynamicSharedMemorySize, GSMEM);
    cudaFuncSetAttribute(pv_kernel,   cudaFuncAttributeMaxDynamicSharedMemorySize, WSMEM);
    cudaFuncSetAttribute(out_kernel,  cudaFuncAttributeMaxDynamicSharedMemorySize, WSMEM);
    cudaFuncSetAttribute(s_softmax_kernel, cudaFuncAttributeMaxDynamicSharedMemorySize, S_SMEM);

    // K0: weight transpose/convert + x -> bf16
    {
        int total = NPROJ * C_IN + C_IN * CV;
        prep_kernel<<<(total + 255) / 256, 256>>>(w_theta, w_phi, w_g, w_o);
    }
    xbf_kernel<<<(M_TOT * C_IN / 8) / 256, 256>>>(x);
    // K1: projections
    proj_kernel<<<dim3(NPROJ / 128, M_TOT / 128), 256, GSMEM>>>();
    // K2: pooling
    poolphi_kernel<<<(8 * HWP * CK) / 256, 256>>>();
    poolvT_kernel<<<dim3(HWP / 64, CV / 32, 8), 256>>>();
    // K3: S + softmax -> P
    s_softmax_kernel<<<dim3(HW / 16, 8), 256, S_SMEM>>>();
    // K4: P @ V  (128x256 tile, P read once)
    pv_kernel<<<dim3(HW / 128, 8), 512, WSMEM>>>();
    // K5: output projection + residual (128x256 tile)
    out_kernel<<<dim3(C_IN / 256, M_TOT / 128), 512, WSMEM>>>(x, gamma, out);
}